// round 5
// baseline (speedup 1.0000x reference)
#include <cuda_runtime.h>
#include <math.h>

// GRNNTransformGated: 13-level binary-tree GRNN, fp32 + packed f32x2 FMA.
// 512 threads/block; RPT=4 (64 rows) for big levels, RPT=1 (16 rows) for small.

#define NTHR 512
#define SB 260

__device__ float g_upA[262144 * 64];
__device__ float g_upB[131072 * 64];

// ---------- packed f32x2 helpers ----------
__device__ __forceinline__ unsigned long long pk2(float a, float b) {
    unsigned long long r;
    asm("mov.b64 %0, {%1, %2};" : "=l"(r) : "f"(a), "f"(b));
    return r;
}
__device__ __forceinline__ float2 upk2(unsigned long long v) {
    float2 f;
    asm("mov.b64 {%0, %1}, %2;" : "=f"(f.x), "=f"(f.y) : "l"(v));
    return f;
}
__device__ __forceinline__ unsigned long long fma2(unsigned long long a,
                                                   unsigned long long b,
                                                   unsigned long long c) {
    unsigned long long d;
    asm("fma.rn.f32x2 %0, %1, %2, %3;" : "=l"(d) : "l"(a), "l"(b), "l"(c));
    return d;
}

// ---------------- top level (j=12) ----------------
__global__ void grnn_top_kernel(const float* __restrict__ contents,
                                const float* __restrict__ W_u,
                                const float* __restrict__ b_u,
                                float* __restrict__ up, int n) {
    int idx = blockIdx.x * blockDim.x + threadIdx.x;
    if (idx >= n * 64) return;
    int i = idx >> 6, h = idx & 63;
    const float* c = contents + (size_t)i * 7;
    const float* w = W_u + h * 7;
    float acc = b_u[h];
#pragma unroll
    for (int f = 0; f < 7; f++) acc = fmaf(__ldg(c + f), __ldg(w + f), acc);
    up[idx] = fmaxf(acc, 0.f);
}

// ---------------- fused level kernel: ROWS = 16*RPT rows / block ----------------
template <int RPT>
__global__ __launch_bounds__(NTHR) void grnn_level_kernel(
    const float* __restrict__ contents,
    const float* __restrict__ up_prev,
    float* __restrict__ up_out,
    const float* __restrict__ W_u, const float* __restrict__ b_u,
    const float* __restrict__ W_r, const float* __restrict__ b_r,
    const float* __restrict__ W_h, const float* __restrict__ b_h,
    const float* __restrict__ W_z, const float* __restrict__ b_z)
{
    constexpr int ROWS = 16 * RPT;
    extern __shared__ float sm[];
    float* hhu = sm;                       // ROWS*192
    float* rx  = hhu + ROWS * 192;         // ROWS*192
    float* hH  = rx  + ROWS * 192;         // ROWS*64
    float* Bs0 = hH  + ROWS * 64;          // 16*SB
    float* Bs1 = Bs0 + 16 * SB;            // 16*SB
    float* cs  = Bs1 + 16 * SB;            // ROWS*8
    float* wu  = cs  + ROWS * 8;           // 64*8
    float* bus = wu  + 64 * 8;             // 64

    const int t  = threadIdx.x;
    const int tx = t & 31, ty = t >> 5;    // 32 col-groups x 16 row-groups
    const int r0 = blockIdx.x * ROWS;

    // ---- phase 0: build hhu = [h_L | h_R | u] ----
    for (int idx = t; idx < ROWS * 7; idx += NTHR) {
        int i = idx / 7, f = idx % 7;
        cs[i * 8 + f] = contents[(size_t)(r0 + i) * 7 + f];
    }
    for (int idx = t; idx < 64 * 7; idx += NTHR) wu[(idx / 7) * 8 + (idx % 7)] = W_u[idx];
    if (t < 64) bus[t] = b_u[t];
    for (int idx = t; idx < ROWS * 128; idx += NTHR) {
        int i = idx >> 7, c = idx & 127;
        hhu[i * 192 + c] = up_prev[((size_t)2 * (r0 + i) + (c >> 6)) * 64 + (c & 63)];
    }
    __syncthreads();
    for (int idx = t; idx < ROWS * 64; idx += NTHR) {
        int i = idx >> 6, h = idx & 63;
        float acc = bus[h];
#pragma unroll
        for (int f = 0; f < 7; f++) acc = fmaf(cs[i * 8 + f], wu[h * 8 + f], acc);
        hhu[i * 192 + 128 + h] = fmaxf(acc, 0.f);
    }
    __syncthreads();

    // ---- phase 1: rx = sigmoid(hhu @ W_r^T + b_r) * hhu  (O=192, K=192) ----
    {
        unsigned long long acc2[RPT][3];
#pragma unroll
        for (int j = 0; j < RPT; j++)
#pragma unroll
            for (int m = 0; m < 3; m++) acc2[j][m] = 0ull;

        auto stage1 = [&](float* B, int kc) {
            for (int e = t; e < 192 * 4; e += NTHR) {
                int o = e >> 2, kq = (e & 3) * 4;
                float4 v = *reinterpret_cast<const float4*>(&W_r[o * 192 + kc * 16 + kq]);
                B[(kq + 0) * SB + o] = v.x; B[(kq + 1) * SB + o] = v.y;
                B[(kq + 2) * SB + o] = v.z; B[(kq + 3) * SB + o] = v.w;
            }
        };
        stage1(Bs0, 0);
        __syncthreads();
        for (int kc = 0; kc < 12; kc++) {
            float* Bc = (kc & 1) ? Bs1 : Bs0;
            float* Bn = (kc & 1) ? Bs0 : Bs1;
            if (kc + 1 < 12) stage1(Bn, kc + 1);
#pragma unroll
            for (int k = 0; k < 16; k++) {
                unsigned long long pa[RPT], b2[3];
#pragma unroll
                for (int j = 0; j < RPT; j++) {
                    float a = hhu[(ty * RPT + j) * 192 + kc * 16 + k];
                    pa[j] = pk2(a, a);
                }
#pragma unroll
                for (int m = 0; m < 3; m++)
                    b2[m] = *reinterpret_cast<const unsigned long long*>(&Bc[k * SB + tx * 6 + 2 * m]);
#pragma unroll
                for (int j = 0; j < RPT; j++)
#pragma unroll
                    for (int m = 0; m < 3; m++) acc2[j][m] = fma2(pa[j], b2[m], acc2[j][m]);
            }
            __syncthreads();
        }
#pragma unroll
        for (int j = 0; j < RPT; j++)
#pragma unroll
            for (int m = 0; m < 3; m++) {
                int i = ty * RPT + j, o = tx * 6 + 2 * m;
                float2 v = upk2(acc2[j][m]);
                float s0 = 1.f / (1.f + __expf(-(v.x + __ldg(b_r + o))));
                float s1 = 1.f / (1.f + __expf(-(v.y + __ldg(b_r + o + 1))));
                rx[i * 192 + o]     = s0 * hhu[i * 192 + o];
                rx[i * 192 + o + 1] = s1 * hhu[i * 192 + o + 1];
            }
    }

    // ---- phase 2: h_H = relu(rx @ W_h^T + b_h)  (O=64, K=192) ----
    {
        unsigned long long acc2[RPT];
#pragma unroll
        for (int j = 0; j < RPT; j++) acc2[j] = 0ull;

        auto stage2 = [&](float* B, int kc) {
            if (t < 64 * 4) {
                int o = t >> 2, kq = (t & 3) * 4;
                float4 v = *reinterpret_cast<const float4*>(&W_h[o * 192 + kc * 16 + kq]);
                B[(kq + 0) * SB + o] = v.x; B[(kq + 1) * SB + o] = v.y;
                B[(kq + 2) * SB + o] = v.z; B[(kq + 3) * SB + o] = v.w;
            }
        };
        stage2(Bs0, 0);
        __syncthreads();
        for (int kc = 0; kc < 12; kc++) {
            float* Bc = (kc & 1) ? Bs1 : Bs0;
            float* Bn = (kc & 1) ? Bs0 : Bs1;
            if (kc + 1 < 12) stage2(Bn, kc + 1);
#pragma unroll
            for (int k = 0; k < 16; k++) {
                unsigned long long b2 =
                    *reinterpret_cast<const unsigned long long*>(&Bc[k * SB + tx * 2]);
#pragma unroll
                for (int j = 0; j < RPT; j++) {
                    float a = rx[(ty * RPT + j) * 192 + kc * 16 + k];
                    acc2[j] = fma2(pk2(a, a), b2, acc2[j]);
                }
            }
            __syncthreads();
        }
#pragma unroll
        for (int j = 0; j < RPT; j++) {
            int i = ty * RPT + j, o = tx * 2;
            float2 v = upk2(acc2[j]);
            hH[i * 64 + o]     = fmaxf(v.x + __ldg(b_h + o), 0.f);
            hH[i * 64 + o + 1] = fmaxf(v.y + __ldg(b_h + o + 1), 0.f);
        }
    }

    // ---- phase 3: z = [h_H | hhu] @ W_z^T + b_z; softmax; combine ----
    {
        unsigned long long acc2[RPT][4];
#pragma unroll
        for (int j = 0; j < RPT; j++)
#pragma unroll
            for (int m = 0; m < 4; m++) acc2[j][m] = 0ull;

        auto stage3 = [&](float* B, int kc) {
            for (int e = t; e < 256 * 4; e += NTHR) {
                int o = e >> 2, kq = (e & 3) * 4;
                float4 v = *reinterpret_cast<const float4*>(&W_z[o * 256 + kc * 16 + kq]);
                B[(kq + 0) * SB + o] = v.x; B[(kq + 1) * SB + o] = v.y;
                B[(kq + 2) * SB + o] = v.z; B[(kq + 3) * SB + o] = v.w;
            }
        };
        stage3(Bs0, 0);
        __syncthreads();
        for (int kc = 0; kc < 16; kc++) {
            float* Bc = (kc & 1) ? Bs1 : Bs0;
            float* Bn = (kc & 1) ? Bs0 : Bs1;
            if (kc + 1 < 16) stage3(Bn, kc + 1);
            const float* Ab; int astr, koff;
            if (kc < 4) { Ab = hH;  astr = 64;  koff = kc * 16; }
            else        { Ab = hhu; astr = 192; koff = kc * 16 - 64; }
#pragma unroll
            for (int k = 0; k < 16; k++) {
                unsigned long long pa[RPT], b2[4];
#pragma unroll
                for (int j = 0; j < RPT; j++) {
                    float a = Ab[(ty * RPT + j) * astr + koff + k];
                    pa[j] = pk2(a, a);
                }
#pragma unroll
                for (int g = 0; g < 4; g++)
                    b2[g] = *reinterpret_cast<const unsigned long long*>(&Bc[k * SB + g * 64 + tx * 2]);
#pragma unroll
                for (int j = 0; j < RPT; j++)
#pragma unroll
                    for (int g = 0; g < 4; g++) acc2[j][g] = fma2(pa[j], b2[g], acc2[j][g]);
            }
            __syncthreads();
        }
        // epilogue: softmax over {h_H, h_L, h_R, u}, gated combine, store
#pragma unroll
        for (int j = 0; j < RPT; j++) {
            int i = ty * RPT + j;
            float zv[4][2];
#pragma unroll
            for (int g = 0; g < 4; g++) {
                float2 v = upk2(acc2[j][g]);
                zv[g][0] = v.x; zv[g][1] = v.y;
            }
            float res[2];
#pragma unroll
            for (int m = 0; m < 2; m++) {
                int h = tx * 2 + m;
                float v0 = zv[0][m] + __ldg(b_z +   0 + h);
                float v1 = zv[1][m] + __ldg(b_z +  64 + h);
                float v2 = zv[2][m] + __ldg(b_z + 128 + h);
                float v3 = zv[3][m] + __ldg(b_z + 192 + h);
                float mx = fmaxf(fmaxf(v0, v1), fmaxf(v2, v3));
                float e0 = __expf(v0 - mx), e1 = __expf(v1 - mx);
                float e2 = __expf(v2 - mx), e3 = __expf(v3 - mx);
                float inv = 1.f / (e0 + e1 + e2 + e3);
                float hhv = hH[i * 64 + h];
                float hlv = hhu[i * 192 + h];
                float hrv = hhu[i * 192 + 64 + h];
                float uv  = hhu[i * 192 + 128 + h];
                res[m] = (e0 * hhv + e1 * hlv + e2 * hrv + e3 * uv) * inv;
            }
            *reinterpret_cast<float2*>(&up_out[(size_t)(r0 + i) * 64 + tx * 2]) =
                make_float2(res[0], res[1]);
        }
    }
}

static int smem_bytes(int rows) {
    return (rows * 192 * 2 + rows * 64 + 2 * 16 * SB + rows * 8 + 64 * 8 + 64) * (int)sizeof(float);
}

extern "C" void kernel_launch(void* const* d_in, const int* in_sizes, int n_in,
                              void* d_out, int out_size) {
    const float* contents = (const float*)d_in[0];
    const float* W_u = (const float*)d_in[1];
    const float* b_u = (const float*)d_in[2];
    const float* W_r = (const float*)d_in[3];
    const float* b_r = (const float*)d_in[4];
    const float* W_h = (const float*)d_in[5];
    const float* b_h = (const float*)d_in[6];
    const float* W_z = (const float*)d_in[7];
    const float* b_z = (const float*)d_in[8];
    float* out = (float*)d_out;

    float* upA = nullptr;
    float* upB = nullptr;
    cudaGetSymbolAddress((void**)&upA, g_upA);
    cudaGetSymbolAddress((void**)&upB, g_upB);

    const int smemBig = smem_bytes(64), smemSmall = smem_bytes(16);
    cudaFuncSetAttribute(grnn_level_kernel<4>,
                         cudaFuncAttributeMaxDynamicSharedMemorySize, smemBig);
    cudaFuncSetAttribute(grnn_level_kernel<1>,
                         cudaFuncAttributeMaxDynamicSharedMemorySize, smemSmall);

    // Level 12 (top): up = u
    {
        int n = 64 << 12;
        size_t off = (size_t)64 * ((1 << 12) - 1) * 7;
        int total = n * 64;
        grnn_top_kernel<<<(total + 255) / 256, 256>>>(contents + off, W_u, b_u, upA, n);
    }

    // Levels 11..0
    const float* prev = upA;
    for (int j = 11; j >= 0; j--) {
        int n = 64 << j;
        size_t off = (size_t)64 * ((1 << j) - 1) * 7;
        float* outp = (j == 0) ? out : ((j & 1) ? upB : upA);
        if (n > 8192) {
            grnn_level_kernel<4><<<n / 64, NTHR, smemBig>>>(
                contents + off, prev, outp,
                W_u, b_u, W_r, b_r, W_h, b_h, W_z, b_z);
        } else {
            grnn_level_kernel<1><<<n / 16, NTHR, smemSmall>>>(
                contents + off, prev, outp,
                W_u, b_u, W_r, b_r, W_h, b_h, W_z, b_z);
        }
        prev = outp;
    }
}

// round 6
// speedup vs baseline: 1.3709x; 1.3709x over previous
#include <cuda_runtime.h>
#include <cuda_bf16.h>
#include <math.h>

// GRNNTransformGated via mma.sync.m16n8k16 bf16 (3-pass split ~ fp32 precision).
// 64 rows/block, 256 threads (8 warps, 2m x 4n warp grid).

#define NTHR 256
#define SAB 528   // A buf row stride bytes (264 bf16, K<=256)
#define SRB 400   // rx buf row stride bytes (200 bf16, K=192)

__device__ float g_upA[262144 * 64];
__device__ float g_upB[131072 * 64];

// smem layout (bytes)
#define OF_AHI 0
#define OF_ALO (OF_AHI + 64 * SAB)       // 33792
#define OF_RHI (OF_ALO + 64 * SAB)       // 67584
#define OF_RLO (OF_RHI + 64 * SRB)       // 93184
#define OF_BHI (OF_RLO + 64 * SRB)       // 118784
#define OF_BLO (OF_BHI + 64 * SAB)       // 152576
#define OF_CS  (OF_BLO + 64 * SAB)       // 186368
#define OF_WU  (OF_CS + 64 * 8 * 4)      // 188416
#define OF_BUS (OF_WU + 64 * 8 * 4)      // 190464
#define SMEM_TOTAL (OF_BUS + 256)        // 190720

__device__ __forceinline__ void split_pack(float a, float b, unsigned& hi, unsigned& lo) {
    __nv_bfloat16 ha = __float2bfloat16(a), hb = __float2bfloat16(b);
    __nv_bfloat16 la = __float2bfloat16(a - __bfloat162float(ha));
    __nv_bfloat16 lb = __float2bfloat16(b - __bfloat162float(hb));
    hi = (unsigned)__bfloat16_as_ushort(ha) | ((unsigned)__bfloat16_as_ushort(hb) << 16);
    lo = (unsigned)__bfloat16_as_ushort(la) | ((unsigned)__bfloat16_as_ushort(lb) << 16);
}
__device__ __forceinline__ float rd_split(const char* hi, const char* lo, int row, int col, int strideB) {
    return __bfloat162float(*(const __nv_bfloat16*)(hi + row * strideB + col * 2)) +
           __bfloat162float(*(const __nv_bfloat16*)(lo + row * strideB + col * 2));
}
__device__ __forceinline__ void mma16816(float* c, const unsigned* a, const unsigned* b) {
    asm volatile("mma.sync.aligned.m16n8k16.row.col.f32.bf16.bf16.f32 "
                 "{%0,%1,%2,%3}, {%4,%5,%6,%7}, {%8,%9}, {%0,%1,%2,%3};"
                 : "+f"(c[0]), "+f"(c[1]), "+f"(c[2]), "+f"(c[3])
                 : "r"(a[0]), "r"(a[1]), "r"(a[2]), "r"(a[3]), "r"(b[0]), "r"(b[1]));
}

// stage 64 rows of W[n0..n0+64) x K (fp32, row stride K) into BHI/BLO bf16 split
__device__ __forceinline__ void stageW(char* BHI, char* BLO, const float* __restrict__ W,
                                       int n0, int K, int t) {
    int q = K >> 2;
    for (int e = t; e < 64 * q; e += NTHR) {
        int n = e / q, k = (e % q) * 4;
        float4 w = *(const float4*)(W + (size_t)(n0 + n) * K + k);
        unsigned h0, l0, h1, l1;
        split_pack(w.x, w.y, h0, l0); split_pack(w.z, w.w, h1, l1);
        *(uint2*)(BHI + n * SAB + k * 2) = make_uint2(h0, h1);
        *(uint2*)(BLO + n * SAB + k * 2) = make_uint2(l0, l1);
    }
}

// one N=64 chunk GEMM: acc[2][2][4] += A[64 x 16*Ksteps] @ B^T, 3-pass bf16 split
__device__ __forceinline__ void gemm_chunk(
    const char* AHI, const char* ALO, int strideA, int aoff,
    const char* BHI, const char* BLO,
    int Ksteps, int wm, int wn, int g, int tg, float acc[2][2][4])
{
    for (int kk = 0; kk < Ksteps; kk++) {
        int kb = (aoff + kk * 16 + 2 * tg) * 2;
        unsigned ah[2][4], al[2][4], bh[2][2], bl[2][2];
#pragma unroll
        for (int mt = 0; mt < 2; mt++) {
            int r = wm * 32 + mt * 16 + g;
            const char* p0 = AHI + r * strideA + kb;
            const char* p1 = p0 + 8 * strideA;
            ah[mt][0] = *(const unsigned*)p0;       ah[mt][1] = *(const unsigned*)p1;
            ah[mt][2] = *(const unsigned*)(p0 + 16); ah[mt][3] = *(const unsigned*)(p1 + 16);
            const char* q0 = ALO + r * strideA + kb;
            const char* q1 = q0 + 8 * strideA;
            al[mt][0] = *(const unsigned*)q0;       al[mt][1] = *(const unsigned*)q1;
            al[mt][2] = *(const unsigned*)(q0 + 16); al[mt][3] = *(const unsigned*)(q1 + 16);
        }
        int kbB = (kk * 16 + 2 * tg) * 2;
#pragma unroll
        for (int nt = 0; nt < 2; nt++) {
            int n = wn * 16 + nt * 8 + g;
            const char* p = BHI + n * SAB + kbB;
            bh[nt][0] = *(const unsigned*)p; bh[nt][1] = *(const unsigned*)(p + 16);
            const char* q = BLO + n * SAB + kbB;
            bl[nt][0] = *(const unsigned*)q; bl[nt][1] = *(const unsigned*)(q + 16);
        }
#pragma unroll
        for (int mt = 0; mt < 2; mt++)
#pragma unroll
            for (int nt = 0; nt < 2; nt++) {
                mma16816(acc[mt][nt], ah[mt], bh[nt]);
                mma16816(acc[mt][nt], ah[mt], bl[nt]);
                mma16816(acc[mt][nt], al[mt], bh[nt]);
            }
    }
}

// ---------------- top level (j=12) ----------------
__global__ void grnn_top_kernel(const float* __restrict__ contents,
                                const float* __restrict__ W_u,
                                const float* __restrict__ b_u,
                                float* __restrict__ up, int n) {
    int idx = blockIdx.x * blockDim.x + threadIdx.x;
    if (idx >= n * 64) return;
    int i = idx >> 6, h = idx & 63;
    const float* c = contents + (size_t)i * 7;
    const float* w = W_u + h * 7;
    float acc = b_u[h];
#pragma unroll
    for (int f = 0; f < 7; f++) acc = fmaf(__ldg(c + f), __ldg(w + f), acc);
    up[idx] = fmaxf(acc, 0.f);
}

// ---------------- fused level kernel: 64 rows / block ----------------
__global__ __launch_bounds__(NTHR, 1) void grnn_level_kernel(
    const float* __restrict__ contents,
    const float* __restrict__ up_prev,
    float* __restrict__ up_out,
    const float* __restrict__ W_u, const float* __restrict__ b_u,
    const float* __restrict__ W_r, const float* __restrict__ b_r,
    const float* __restrict__ W_h, const float* __restrict__ b_h,
    const float* __restrict__ W_z, const float* __restrict__ b_z)
{
    extern __shared__ char sm[];
    char* AHI = sm + OF_AHI; char* ALO = sm + OF_ALO;
    char* RHI = sm + OF_RHI; char* RLO = sm + OF_RLO;
    char* BHI = sm + OF_BHI; char* BLO = sm + OF_BLO;
    float* cs  = (float*)(sm + OF_CS);
    float* wu  = (float*)(sm + OF_WU);
    float* bus = (float*)(sm + OF_BUS);

    const int t = threadIdx.x, lane = t & 31, w = t >> 5;
    const int wm = w >> 2, wn = w & 3, g = lane >> 2, tg = lane & 3;
    const int r0 = blockIdx.x * 64;

    // ---- phase 0a: stage contents/W_u/b_u; load+split h_L,h_R into AHI/ALO cols 64..191 ----
    for (int idx = t; idx < 64 * 7; idx += NTHR) {
        int i = idx / 7, f = idx % 7;
        cs[i * 8 + f] = contents[(size_t)(r0 + i) * 7 + f];
        wu[i * 8 + f] = W_u[idx];
    }
    if (t < 64) bus[t] = b_u[t];
    for (int idx = t; idx < 64 * 32; idx += NTHR) {
        int i = idx >> 5, q = idx & 31, side = q >> 4, qq = q & 15;
        float4 v = *(const float4*)(up_prev + ((size_t)2 * (r0 + i) + side) * 64 + qq * 4);
        unsigned h0, l0, h1, l1;
        split_pack(v.x, v.y, h0, l0); split_pack(v.z, v.w, h1, l1);
        int col = 64 + side * 64 + qq * 4;
        *(uint2*)(AHI + i * SAB + col * 2) = make_uint2(h0, h1);
        *(uint2*)(ALO + i * SAB + col * 2) = make_uint2(l0, l1);
    }
    __syncthreads();
    // ---- phase 0b: u = relu(c @ W_u^T + b_u) -> AHI cols 192..255; stage W_r chunk 0 ----
    for (int idx = t; idx < 64 * 32; idx += NTHR) {
        int i = idx >> 5, cp = idx & 31;
        float a0 = bus[2 * cp], a1 = bus[2 * cp + 1];
#pragma unroll
        for (int f = 0; f < 7; f++) {
            float cv = cs[i * 8 + f];
            a0 = fmaf(cv, wu[(2 * cp) * 8 + f], a0);
            a1 = fmaf(cv, wu[(2 * cp + 1) * 8 + f], a1);
        }
        a0 = fmaxf(a0, 0.f); a1 = fmaxf(a1, 0.f);
        unsigned hi, lo; split_pack(a0, a1, hi, lo);
        *(unsigned*)(AHI + i * SAB + (192 + 2 * cp) * 2) = hi;
        *(unsigned*)(ALO + i * SAB + (192 + 2 * cp) * 2) = lo;
    }
    stageW(BHI, BLO, W_r, 0, 192, t);
    __syncthreads();

    // ---- GEMM1: rx = sigmoid(hhu @ W_r^T + b_r) * hhu, 3 chunks of N=64 ----
    for (int c = 0; c < 3; c++) {
        float acc[2][2][4] = {};
        gemm_chunk(AHI, ALO, SAB, 64, BHI, BLO, 12, wm, wn, g, tg, acc);
        __syncthreads();
        if (c < 2) stageW(BHI, BLO, W_r, (c + 1) * 64, 192, t);
#pragma unroll
        for (int mt = 0; mt < 2; mt++)
#pragma unroll
            for (int nt = 0; nt < 2; nt++)
#pragma unroll
                for (int rs = 0; rs < 2; rs++) {
                    int row = wm * 32 + mt * 16 + g + rs * 8;
                    int o0 = c * 64 + wn * 16 + nt * 8 + 2 * tg;
                    float z0 = acc[mt][nt][rs * 2 + 0] + __ldg(b_r + o0);
                    float z1 = acc[mt][nt][rs * 2 + 1] + __ldg(b_r + o0 + 1);
                    float s0 = 1.f / (1.f + __expf(-z0));
                    float s1 = 1.f / (1.f + __expf(-z1));
                    float x0 = s0 * rd_split(AHI, ALO, row, 64 + o0, SAB);
                    float x1 = s1 * rd_split(AHI, ALO, row, 64 + o0 + 1, SAB);
                    unsigned hi, lo; split_pack(x0, x1, hi, lo);
                    *(unsigned*)(RHI + row * SRB + o0 * 2) = hi;
                    *(unsigned*)(RLO + row * SRB + o0 * 2) = lo;
                }
        __syncthreads();
    }

    // ---- GEMM2: h_H = relu(rx @ W_h^T + b_h) -> AHI cols 0..63 ----
    stageW(BHI, BLO, W_h, 0, 192, t);
    __syncthreads();
    {
        float acc[2][2][4] = {};
        gemm_chunk(RHI, RLO, SRB, 0, BHI, BLO, 12, wm, wn, g, tg, acc);
#pragma unroll
        for (int mt = 0; mt < 2; mt++)
#pragma unroll
            for (int nt = 0; nt < 2; nt++)
#pragma unroll
                for (int rs = 0; rs < 2; rs++) {
                    int row = wm * 32 + mt * 16 + g + rs * 8;
                    int h0 = wn * 16 + nt * 8 + 2 * tg;
                    float v0 = fmaxf(acc[mt][nt][rs * 2 + 0] + __ldg(b_h + h0), 0.f);
                    float v1 = fmaxf(acc[mt][nt][rs * 2 + 1] + __ldg(b_h + h0 + 1), 0.f);
                    unsigned hi, lo; split_pack(v0, v1, hi, lo);
                    *(unsigned*)(AHI + row * SAB + h0 * 2) = hi;
                    *(unsigned*)(ALO + row * SAB + h0 * 2) = lo;
                }
    }
    __syncthreads();

    // ---- GEMM3: z = [h_H | hhu] @ W_z^T + b_z, 4 chunks (one per softmax group) ----
    float acc3[4][2][2][4] = {};
    stageW(BHI, BLO, W_z, 0, 256, t);
    __syncthreads();
    for (int c = 0; c < 4; c++) {
        gemm_chunk(AHI, ALO, SAB, 0, BHI, BLO, 16, wm, wn, g, tg, acc3[c]);
        __syncthreads();
        if (c < 3) { stageW(BHI, BLO, W_z, (c + 1) * 64, 256, t); __syncthreads(); }
    }

    // ---- final: softmax over 4 groups, gated combine, store fp32 ----
#pragma unroll
    for (int mt = 0; mt < 2; mt++)
#pragma unroll
        for (int nt = 0; nt < 2; nt++)
#pragma unroll
            for (int rs = 0; rs < 2; rs++) {
                int row = wm * 32 + mt * 16 + g + rs * 8;
                int h0 = wn * 16 + nt * 8 + 2 * tg;
                float res[2];
#pragma unroll
                for (int e = 0; e < 2; e++) {
                    int h = h0 + e;
                    float v0 = acc3[0][mt][nt][rs * 2 + e] + __ldg(b_z + h);
                    float v1 = acc3[1][mt][nt][rs * 2 + e] + __ldg(b_z + 64 + h);
                    float v2 = acc3[2][mt][nt][rs * 2 + e] + __ldg(b_z + 128 + h);
                    float v3 = acc3[3][mt][nt][rs * 2 + e] + __ldg(b_z + 192 + h);
                    float mx = fmaxf(fmaxf(v0, v1), fmaxf(v2, v3));
                    float e0 = __expf(v0 - mx), e1 = __expf(v1 - mx);
                    float e2 = __expf(v2 - mx), e3 = __expf(v3 - mx);
                    float inv = 1.f / (e0 + e1 + e2 + e3);
                    float hh = rd_split(AHI, ALO, row, h, SAB);
                    float hl = rd_split(AHI, ALO, row, 64 + h, SAB);
                    float hr = rd_split(AHI, ALO, row, 128 + h, SAB);
                    float uu = rd_split(AHI, ALO, row, 192 + h, SAB);
                    res[e] = (e0 * hh + e1 * hl + e2 * hr + e3 * uu) * inv;
                }
                *(float2*)(up_out + (size_t)(r0 + row) * 64 + h0) = make_float2(res[0], res[1]);
            }
}

extern "C" void kernel_launch(void* const* d_in, const int* in_sizes, int n_in,
                              void* d_out, int out_size) {
    const float* contents = (const float*)d_in[0];
    const float* W_u = (const float*)d_in[1];
    const float* b_u = (const float*)d_in[2];
    const float* W_r = (const float*)d_in[3];
    const float* b_r = (const float*)d_in[4];
    const float* W_h = (const float*)d_in[5];
    const float* b_h = (const float*)d_in[6];
    const float* W_z = (const float*)d_in[7];
    const float* b_z = (const float*)d_in[8];
    float* out = (float*)d_out;

    float* upA = nullptr;
    float* upB = nullptr;
    cudaGetSymbolAddress((void**)&upA, g_upA);
    cudaGetSymbolAddress((void**)&upB, g_upB);

    cudaFuncSetAttribute(grnn_level_kernel,
                         cudaFuncAttributeMaxDynamicSharedMemorySize, SMEM_TOTAL);

    // Level 12 (top): up = u
    {
        int n = 64 << 12;
        size_t off = (size_t)64 * ((1 << 12) - 1) * 7;
        int total = n * 64;
        grnn_top_kernel<<<(total + 255) / 256, 256>>>(contents + off, W_u, b_u, upA, n);
    }

    // Levels 11..0
    const float* prev = upA;
    for (int j = 11; j >= 0; j--) {
        int n = 64 << j;
        size_t off = (size_t)64 * ((1 << j) - 1) * 7;
        float* outp = (j == 0) ? out : ((j & 1) ? upB : upA);
        grnn_level_kernel<<<n / 64, NTHR, SMEM_TOTAL>>>(
            contents + off, prev, outp,
            W_u, b_u, W_r, b_r, W_h, b_h, W_z, b_z);
        prev = outp;
    }
}

// round 7
// speedup vs baseline: 1.6523x; 1.2053x over previous
#include <cuda_runtime.h>
#include <cuda_bf16.h>
#include <math.h>

// GRNNTransformGated via mma.sync.m16n8k16 bf16 (3-pass split ~ fp32 precision).
// 512 threads (16 warps, 2m x 8n warp grid), ROWS=64 big levels / 32 small.

#define NTHR 512
#define SAB 528   // A buf row stride bytes (264 bf16, K<=256)
#define SRB 400   // rx buf row stride bytes (200 bf16, K=192)

__device__ float g_upA[262144 * 64];
__device__ float g_upB[131072 * 64];

__device__ __forceinline__ void split_pack(float a, float b, unsigned& hi, unsigned& lo) {
    __nv_bfloat16 ha = __float2bfloat16(a), hb = __float2bfloat16(b);
    __nv_bfloat16 la = __float2bfloat16(a - __bfloat162float(ha));
    __nv_bfloat16 lb = __float2bfloat16(b - __bfloat162float(hb));
    hi = (unsigned)__bfloat16_as_ushort(ha) | ((unsigned)__bfloat16_as_ushort(hb) << 16);
    lo = (unsigned)__bfloat16_as_ushort(la) | ((unsigned)__bfloat16_as_ushort(lb) << 16);
}
__device__ __forceinline__ float rd_split(const char* hi, const char* lo, int row, int col, int strideB) {
    return __bfloat162float(*(const __nv_bfloat16*)(hi + row * strideB + col * 2)) +
           __bfloat162float(*(const __nv_bfloat16*)(lo + row * strideB + col * 2));
}
__device__ __forceinline__ void mma16816(float* c, const unsigned* a, const unsigned* b) {
    asm volatile("mma.sync.aligned.m16n8k16.row.col.f32.bf16.bf16.f32 "
                 "{%0,%1,%2,%3}, {%4,%5,%6,%7}, {%8,%9}, {%0,%1,%2,%3};"
                 : "+f"(c[0]), "+f"(c[1]), "+f"(c[2]), "+f"(c[3])
                 : "r"(a[0]), "r"(a[1]), "r"(a[2]), "r"(a[3]), "r"(b[0]), "r"(b[1]));
}

// stage 64 rows of W[n0..n0+64) x K (fp32, row stride K) into BHI/BLO bf16 split
__device__ __forceinline__ void stageW(char* BHI, char* BLO, const float* __restrict__ W,
                                       int n0, int K, int t) {
    int q = K >> 2;
    for (int e = t; e < 64 * q; e += NTHR) {
        int n = e / q, k = (e % q) * 4;
        float4 w = *(const float4*)(W + (size_t)(n0 + n) * K + k);
        unsigned h0, l0, h1, l1;
        split_pack(w.x, w.y, h0, l0); split_pack(w.z, w.w, h1, l1);
        *(uint2*)(BHI + n * SAB + k * 2) = make_uint2(h0, h1);
        *(uint2*)(BLO + n * SAB + k * 2) = make_uint2(l0, l1);
    }
}

// N=64 chunk GEMM, warp handles MT m-tiles x one 8-wide n-tile; 3-pass bf16 split
template <int KS, int MT>
__device__ __forceinline__ void gemm_chunk(
    const char* AHI, const char* ALO, int strideA, int aoff,
    const char* BHI, const char* BLO,
    int wm, int wn, int g, int tg, float acc[MT][4])
{
#pragma unroll 2
    for (int kk = 0; kk < KS; kk++) {
        int kb = (aoff + kk * 16 + 2 * tg) * 2;
        unsigned ah[MT][4], al[MT][4], bh[2], bl[2];
#pragma unroll
        for (int mt = 0; mt < MT; mt++) {
            int r = (wm * MT + mt) * 16 + g;
            const char* p0 = AHI + r * strideA + kb;
            const char* p1 = p0 + 8 * strideA;
            ah[mt][0] = *(const unsigned*)p0;        ah[mt][1] = *(const unsigned*)p1;
            ah[mt][2] = *(const unsigned*)(p0 + 16); ah[mt][3] = *(const unsigned*)(p1 + 16);
            const char* q0 = ALO + r * strideA + kb;
            const char* q1 = q0 + 8 * strideA;
            al[mt][0] = *(const unsigned*)q0;        al[mt][1] = *(const unsigned*)q1;
            al[mt][2] = *(const unsigned*)(q0 + 16); al[mt][3] = *(const unsigned*)(q1 + 16);
        }
        int kbB = (kk * 16 + 2 * tg) * 2;
        {
            int n = wn * 8 + g;
            const char* p = BHI + n * SAB + kbB;
            bh[0] = *(const unsigned*)p; bh[1] = *(const unsigned*)(p + 16);
            const char* q = BLO + n * SAB + kbB;
            bl[0] = *(const unsigned*)q; bl[1] = *(const unsigned*)(q + 16);
        }
#pragma unroll
        for (int mt = 0; mt < MT; mt++) {
            mma16816(acc[mt], ah[mt], bh);
            mma16816(acc[mt], ah[mt], bl);
            mma16816(acc[mt], al[mt], bh);
        }
    }
}

// ---------------- top level (j=12) ----------------
__global__ void grnn_top_kernel(const float* __restrict__ contents,
                                const float* __restrict__ W_u,
                                const float* __restrict__ b_u,
                                float* __restrict__ up, int n) {
    int idx = blockIdx.x * blockDim.x + threadIdx.x;
    if (idx >= n * 64) return;
    int i = idx >> 6, h = idx & 63;
    const float* c = contents + (size_t)i * 7;
    const float* w = W_u + h * 7;
    float acc = b_u[h];
#pragma unroll
    for (int f = 0; f < 7; f++) acc = fmaf(__ldg(c + f), __ldg(w + f), acc);
    up[idx] = fmaxf(acc, 0.f);
}

// ---------------- fused level kernel: ROWS rows / block, 512 threads ----------------
template <int ROWS>
__global__ __launch_bounds__(NTHR, 1) void grnn_level_kernel(
    const float* __restrict__ contents,
    const float* __restrict__ up_prev,
    float* __restrict__ up_out,
    const float* __restrict__ W_u, const float* __restrict__ b_u,
    const float* __restrict__ W_r, const float* __restrict__ b_r,
    const float* __restrict__ W_h, const float* __restrict__ b_h,
    const float* __restrict__ W_z, const float* __restrict__ b_z)
{
    constexpr int MT = ROWS / 32;
    constexpr int OF_ALO = ROWS * SAB;
    constexpr int OF_RHI = OF_ALO + ROWS * SAB;
    constexpr int OF_RLO = OF_RHI + ROWS * SRB;
    constexpr int OF_BHI = OF_RLO + ROWS * SRB;
    constexpr int OF_BLO = OF_BHI + 64 * SAB;
    constexpr int OF_CS  = OF_BLO + 64 * SAB;
    constexpr int OF_WU  = OF_CS + ROWS * 8 * 4;
    constexpr int OF_BUS = OF_WU + 64 * 8 * 4;

    extern __shared__ char sm[];
    char* AHI = sm;            char* ALO = sm + OF_ALO;
    char* RHI = sm + OF_RHI;   char* RLO = sm + OF_RLO;
    char* BHI = sm + OF_BHI;   char* BLO = sm + OF_BLO;
    float* cs  = (float*)(sm + OF_CS);
    float* wu  = (float*)(sm + OF_WU);
    float* bus = (float*)(sm + OF_BUS);

    const int t = threadIdx.x, lane = t & 31, w = t >> 5;
    const int wm = w >> 3, wn = w & 7, g = lane >> 2, tg = lane & 3;
    const int r0 = blockIdx.x * ROWS;

    // ---- phase 0a ----
    for (int idx = t; idx < ROWS * 7; idx += NTHR) {
        int i = idx / 7, f = idx % 7;
        cs[i * 8 + f] = contents[(size_t)(r0 + i) * 7 + f];
    }
    for (int idx = t; idx < 64 * 7; idx += NTHR) wu[(idx / 7) * 8 + (idx % 7)] = W_u[idx];
    if (t < 64) bus[t] = b_u[t];
    for (int idx = t; idx < ROWS * 32; idx += NTHR) {
        int i = idx >> 5, q = idx & 31, side = q >> 4, qq = q & 15;
        float4 v = *(const float4*)(up_prev + ((size_t)2 * (r0 + i) + side) * 64 + qq * 4);
        unsigned h0, l0, h1, l1;
        split_pack(v.x, v.y, h0, l0); split_pack(v.z, v.w, h1, l1);
        int col = 64 + side * 64 + qq * 4;
        *(uint2*)(AHI + i * SAB + col * 2) = make_uint2(h0, h1);
        *(uint2*)(ALO + i * SAB + col * 2) = make_uint2(l0, l1);
    }
    __syncthreads();
    // ---- phase 0b: u = relu(c @ W_u^T + b_u) -> cols 192..255; stage W_r chunk 0 ----
    for (int idx = t; idx < ROWS * 32; idx += NTHR) {
        int i = idx >> 5, cp = idx & 31;
        float a0 = bus[2 * cp], a1 = bus[2 * cp + 1];
#pragma unroll
        for (int f = 0; f < 7; f++) {
            float cv = cs[i * 8 + f];
            a0 = fmaf(cv, wu[(2 * cp) * 8 + f], a0);
            a1 = fmaf(cv, wu[(2 * cp + 1) * 8 + f], a1);
        }
        a0 = fmaxf(a0, 0.f); a1 = fmaxf(a1, 0.f);
        unsigned hi, lo; split_pack(a0, a1, hi, lo);
        *(unsigned*)(AHI + i * SAB + (192 + 2 * cp) * 2) = hi;
        *(unsigned*)(ALO + i * SAB + (192 + 2 * cp) * 2) = lo;
    }
    stageW(BHI, BLO, W_r, 0, 192, t);
    __syncthreads();

    // ---- GEMM1: rx = sigmoid(hhu @ W_r^T + b_r) * hhu, 3 chunks of N=64 ----
    for (int c = 0; c < 3; c++) {
        float acc[MT][4] = {};
        gemm_chunk<12, MT>(AHI, ALO, SAB, 64, BHI, BLO, wm, wn, g, tg, acc);
        __syncthreads();
        if (c < 2) stageW(BHI, BLO, W_r, (c + 1) * 64, 192, t);
#pragma unroll
        for (int mt = 0; mt < MT; mt++)
#pragma unroll
            for (int rs = 0; rs < 2; rs++) {
                int row = (wm * MT + mt) * 16 + g + rs * 8;
                int o0 = c * 64 + wn * 8 + 2 * tg;
                float z0 = acc[mt][rs * 2 + 0] + __ldg(b_r + o0);
                float z1 = acc[mt][rs * 2 + 1] + __ldg(b_r + o0 + 1);
                float s0 = 1.f / (1.f + __expf(-z0));
                float s1 = 1.f / (1.f + __expf(-z1));
                float x0 = s0 * rd_split(AHI, ALO, row, 64 + o0, SAB);
                float x1 = s1 * rd_split(AHI, ALO, row, 64 + o0 + 1, SAB);
                unsigned hi, lo; split_pack(x0, x1, hi, lo);
                *(unsigned*)(RHI + row * SRB + o0 * 2) = hi;
                *(unsigned*)(RLO + row * SRB + o0 * 2) = lo;
            }
        __syncthreads();
    }

    // ---- GEMM2: h_H = relu(rx @ W_h^T + b_h) -> cols 0..63 ----
    stageW(BHI, BLO, W_h, 0, 192, t);
    __syncthreads();
    {
        float acc[MT][4] = {};
        gemm_chunk<12, MT>(RHI, RLO, SRB, 0, BHI, BLO, wm, wn, g, tg, acc);
#pragma unroll
        for (int mt = 0; mt < MT; mt++)
#pragma unroll
            for (int rs = 0; rs < 2; rs++) {
                int row = (wm * MT + mt) * 16 + g + rs * 8;
                int h0 = wn * 8 + 2 * tg;
                float v0 = fmaxf(acc[mt][rs * 2 + 0] + __ldg(b_h + h0), 0.f);
                float v1 = fmaxf(acc[mt][rs * 2 + 1] + __ldg(b_h + h0 + 1), 0.f);
                unsigned hi, lo; split_pack(v0, v1, hi, lo);
                *(unsigned*)(AHI + row * SAB + h0 * 2) = hi;
                *(unsigned*)(ALO + row * SAB + h0 * 2) = lo;
            }
    }
    __syncthreads();

    // ---- GEMM3: z = [h_H | hhu] @ W_z^T + b_z, 4 chunks (one per softmax group) ----
    float acc3[4][MT][4] = {};
    stageW(BHI, BLO, W_z, 0, 256, t);
    __syncthreads();
    for (int c = 0; c < 4; c++) {
        gemm_chunk<16, MT>(AHI, ALO, SAB, 0, BHI, BLO, wm, wn, g, tg, acc3[c]);
        __syncthreads();
        if (c < 3) { stageW(BHI, BLO, W_z, (c + 1) * 64, 256, t); __syncthreads(); }
    }

    // ---- final: softmax over 4 groups, gated combine, store fp32 ----
#pragma unroll
    for (int mt = 0; mt < MT; mt++)
#pragma unroll
        for (int rs = 0; rs < 2; rs++) {
            int row = (wm * MT + mt) * 16 + g + rs * 8;
            int h0 = wn * 8 + 2 * tg;
            float res[2];
#pragma unroll
            for (int e = 0; e < 2; e++) {
                int h = h0 + e;
                float v0 = acc3[0][mt][rs * 2 + e] + __ldg(b_z + h);
                float v1 = acc3[1][mt][rs * 2 + e] + __ldg(b_z + 64 + h);
                float v2 = acc3[2][mt][rs * 2 + e] + __ldg(b_z + 128 + h);
                float v3 = acc3[3][mt][rs * 2 + e] + __ldg(b_z + 192 + h);
                float mx = fmaxf(fmaxf(v0, v1), fmaxf(v2, v3));
                float e0 = __expf(v0 - mx), e1 = __expf(v1 - mx);
                float e2 = __expf(v2 - mx), e3 = __expf(v3 - mx);
                float inv = 1.f / (e0 + e1 + e2 + e3);
                float hh = rd_split(AHI, ALO, row, h, SAB);
                float hl = rd_split(AHI, ALO, row, 64 + h, SAB);
                float hr = rd_split(AHI, ALO, row, 128 + h, SAB);
                float uu = rd_split(AHI, ALO, row, 192 + h, SAB);
                res[e] = (e0 * hh + e1 * hl + e2 * hr + e3 * uu) * inv;
            }
            *(float2*)(up_out + (size_t)(r0 + row) * 64 + h0) = make_float2(res[0], res[1]);
        }
}

static int smem_sz(int rows) {
    return rows * SAB * 2 + rows * SRB * 2 + 64 * SAB * 2 + rows * 8 * 4 + 64 * 8 * 4 + 256;
}

extern "C" void kernel_launch(void* const* d_in, const int* in_sizes, int n_in,
                              void* d_out, int out_size) {
    const float* contents = (const float*)d_in[0];
    const float* W_u = (const float*)d_in[1];
    const float* b_u = (const float*)d_in[2];
    const float* W_r = (const float*)d_in[3];
    const float* b_r = (const float*)d_in[4];
    const float* W_h = (const float*)d_in[5];
    const float* b_h = (const float*)d_in[6];
    const float* W_z = (const float*)d_in[7];
    const float* b_z = (const float*)d_in[8];
    float* out = (float*)d_out;

    float* upA = nullptr;
    float* upB = nullptr;
    cudaGetSymbolAddress((void**)&upA, g_upA);
    cudaGetSymbolAddress((void**)&upB, g_upB);

    const int smemBig = smem_sz(64), smemSmall = smem_sz(32);
    cudaFuncSetAttribute(grnn_level_kernel<64>,
                         cudaFuncAttributeMaxDynamicSharedMemorySize, smemBig);
    cudaFuncSetAttribute(grnn_level_kernel<32>,
                         cudaFuncAttributeMaxDynamicSharedMemorySize, smemSmall);

    // Level 12 (top): up = u
    {
        int n = 64 << 12;
        size_t off = (size_t)64 * ((1 << 12) - 1) * 7;
        int total = n * 64;
        grnn_top_kernel<<<(total + 255) / 256, 256>>>(contents + off, W_u, b_u, upA, n);
    }

    // Levels 11..0
    const float* prev = upA;
    for (int j = 11; j >= 0; j--) {
        int n = 64 << j;
        size_t off = (size_t)64 * ((1 << j) - 1) * 7;
        float* outp = (j == 0) ? out : ((j & 1) ? upB : upA);
        if (n >= 16384) {
            grnn_level_kernel<64><<<n / 64, NTHR, smemBig>>>(
                contents + off, prev, outp,
                W_u, b_u, W_r, b_r, W_h, b_h, W_z, b_z);
        } else {
            grnn_level_kernel<32><<<n / 32, NTHR, smemSmall>>>(
                contents + off, prev, outp,
                W_u, b_u, W_r, b_r, W_h, b_h, W_z, b_z);
        }
        prev = outp;
    }
}

// round 8
// speedup vs baseline: 2.0025x; 1.2119x over previous
#include <cuda_runtime.h>
#include <cuda_bf16.h>
#include <math.h>

// GRNNTransformGated via mma.sync.m16n8k16 bf16 (3-pass split ~ fp32 precision).
// Weights pre-split to bf16 hi/lo in gmem once; ldmatrix fragment loads.
// 512 threads (16 warps, 2m x 8n warp grid), ROWS=64 big levels / 32 small.

#define NTHR 512
#define SAB 528   // A/B buf row stride bytes (K<=256); 528/4 % 32 = 4 -> ldmatrix conflict-free
#define SRB 400   // rx buf row stride bytes (K=192);  400/4 % 32 = 4 -> conflict-free

__device__ float g_upA[262144 * 64];
__device__ float g_upB[131072 * 64];

// pre-split weights (bf16 hi/lo), [n][K] row-major
__device__ unsigned short g_Wr_hi[36864], g_Wr_lo[36864];
__device__ unsigned short g_Wh_hi[12288], g_Wh_lo[12288];
__device__ unsigned short g_Wz_hi[65536], g_Wz_lo[65536];

__device__ __forceinline__ void split_pack(float a, float b, unsigned& hi, unsigned& lo) {
    __nv_bfloat16 ha = __float2bfloat16(a), hb = __float2bfloat16(b);
    __nv_bfloat16 la = __float2bfloat16(a - __bfloat162float(ha));
    __nv_bfloat16 lb = __float2bfloat16(b - __bfloat162float(hb));
    hi = (unsigned)__bfloat16_as_ushort(ha) | ((unsigned)__bfloat16_as_ushort(hb) << 16);
    lo = (unsigned)__bfloat16_as_ushort(la) | ((unsigned)__bfloat16_as_ushort(lb) << 16);
}
__device__ __forceinline__ float rd_split(const char* hi, const char* lo, int row, int col, int strideB) {
    return __bfloat162float(*(const __nv_bfloat16*)(hi + row * strideB + col * 2)) +
           __bfloat162float(*(const __nv_bfloat16*)(lo + row * strideB + col * 2));
}
__device__ __forceinline__ unsigned smem_u32(const void* p) {
    unsigned a;
    asm("{ .reg .u64 t; cvta.to.shared.u64 t, %1; cvt.u32.u64 %0, t; }" : "=r"(a) : "l"(p));
    return a;
}
__device__ __forceinline__ void mma16816(float* c, const unsigned* a, const unsigned* b) {
    asm volatile("mma.sync.aligned.m16n8k16.row.col.f32.bf16.bf16.f32 "
                 "{%0,%1,%2,%3}, {%4,%5,%6,%7}, {%8,%9}, {%0,%1,%2,%3};"
                 : "+f"(c[0]), "+f"(c[1]), "+f"(c[2]), "+f"(c[3])
                 : "r"(a[0]), "r"(a[1]), "r"(a[2]), "r"(a[3]), "r"(b[0]), "r"(b[1]));
}
#define LDSM_X4(d, addr) \
    asm volatile("ldmatrix.sync.aligned.m8n8.x4.shared.b16 {%0,%1,%2,%3}, [%4];" \
                 : "=r"((d)[0]), "=r"((d)[1]), "=r"((d)[2]), "=r"((d)[3]) : "r"(addr))
#define LDSM_X2(d, addr) \
    asm volatile("ldmatrix.sync.aligned.m8n8.x2.shared.b16 {%0,%1}, [%2];" \
                 : "=r"((d)[0]), "=r"((d)[1]) : "r"(addr))

// ---------------- weight prep: fp32 -> bf16 hi/lo (once per launch) ----------------
__global__ void prep_weights(const float* __restrict__ W_r,
                             const float* __restrict__ W_h,
                             const float* __restrict__ W_z) {
    int i = blockIdx.x * blockDim.x + threadIdx.x;
    float v; unsigned short* ph; unsigned short* pl; int k;
    if (i < 36864)       { v = W_r[i];            ph = g_Wr_hi; pl = g_Wr_lo; k = i; }
    else if (i < 49152)  { v = W_h[i - 36864];    ph = g_Wh_hi; pl = g_Wh_lo; k = i - 36864; }
    else if (i < 114688) { v = W_z[i - 49152];    ph = g_Wz_hi; pl = g_Wz_lo; k = i - 49152; }
    else return;
    __nv_bfloat16 h = __float2bfloat16(v);
    __nv_bfloat16 l = __float2bfloat16(v - __bfloat162float(h));
    ph[k] = __bfloat16_as_ushort(h);
    pl[k] = __bfloat16_as_ushort(l);
}

// stage 64 rows x K bf16 (pre-split) into smem, row stride SAB
__device__ __forceinline__ void stageW(char* BHI, char* BLO,
                                       const unsigned short* __restrict__ Whi,
                                       const unsigned short* __restrict__ Wlo,
                                       int n0, int K, int t) {
    int q = K >> 3;   // uint4 = 8 bf16
    for (int e = t; e < 64 * q; e += NTHR) {
        int n = e / q, k = (e % q) * 8;
        *(uint4*)(BHI + n * SAB + k * 2) = *(const uint4*)(Whi + (size_t)(n0 + n) * K + k);
        *(uint4*)(BLO + n * SAB + k * 2) = *(const uint4*)(Wlo + (size_t)(n0 + n) * K + k);
    }
}

// N=64 chunk GEMM via ldmatrix; warp: MT m-tiles x one 8-wide n-tile; 3-pass bf16 split
template <int KS, int MT>
__device__ __forceinline__ void gemm_chunk(
    unsigned aHI, unsigned aLO, int strideA, int aoff,
    unsigned bHI, unsigned bLO,
    int wm, int wn, int lane, float acc[MT][4])
{
    const int l16 = lane & 15;
    unsigned aH[MT], aL[MT];
#pragma unroll
    for (int mt = 0; mt < MT; mt++) {
        unsigned base = (unsigned)(((wm * MT + mt) * 16 + l16) * strideA + aoff * 2 + ((lane >> 4) & 1) * 16);
        aH[mt] = aHI + base; aL[mt] = aLO + base;
    }
    unsigned bo = (unsigned)((wn * 8 + (lane & 7)) * SAB + ((lane >> 3) & 1) * 16);
    unsigned bH = bHI + bo, bL = bLO + bo;
#pragma unroll 4
    for (int kk = 0; kk < KS; kk++) {
        unsigned ah[MT][4], al[MT][4], bh[2], bl[2];
#pragma unroll
        for (int mt = 0; mt < MT; mt++) {
            LDSM_X4(ah[mt], aH[mt] + kk * 32);
            LDSM_X4(al[mt], aL[mt] + kk * 32);
        }
        LDSM_X2(bh, bH + kk * 32);
        LDSM_X2(bl, bL + kk * 32);
#pragma unroll
        for (int mt = 0; mt < MT; mt++) {
            mma16816(acc[mt], ah[mt], bh);
            mma16816(acc[mt], ah[mt], bl);
            mma16816(acc[mt], al[mt], bh);
        }
    }
}

// ---------------- top level (j=12) ----------------
__global__ void grnn_top_kernel(const float* __restrict__ contents,
                                const float* __restrict__ W_u,
                                const float* __restrict__ b_u,
                                float* __restrict__ up, int n) {
    int idx = blockIdx.x * blockDim.x + threadIdx.x;
    if (idx >= n * 64) return;
    int i = idx >> 6, h = idx & 63;
    const float* c = contents + (size_t)i * 7;
    const float* w = W_u + h * 7;
    float acc = b_u[h];
#pragma unroll
    for (int f = 0; f < 7; f++) acc = fmaf(__ldg(c + f), __ldg(w + f), acc);
    up[idx] = fmaxf(acc, 0.f);
}

// ---------------- fused level kernel: ROWS rows / block, 512 threads ----------------
template <int ROWS>
__global__ __launch_bounds__(NTHR, 1) void grnn_level_kernel(
    const float* __restrict__ contents,
    const float* __restrict__ up_prev,
    float* __restrict__ up_out,
    const float* __restrict__ W_u, const float* __restrict__ b_u,
    const unsigned short* __restrict__ Wr_hi, const unsigned short* __restrict__ Wr_lo,
    const float* __restrict__ b_r,
    const unsigned short* __restrict__ Wh_hi, const unsigned short* __restrict__ Wh_lo,
    const float* __restrict__ b_h,
    const unsigned short* __restrict__ Wz_hi, const unsigned short* __restrict__ Wz_lo,
    const float* __restrict__ b_z)
{
    constexpr int MT = ROWS / 32;
    constexpr int OF_ALO = ROWS * SAB;
    constexpr int OF_RHI = OF_ALO + ROWS * SAB;
    constexpr int OF_RLO = OF_RHI + ROWS * SRB;
    constexpr int OF_BHI = OF_RLO + ROWS * SRB;
    constexpr int OF_BLO = OF_BHI + 64 * SAB;
    constexpr int OF_CS  = OF_BLO + 64 * SAB;
    constexpr int OF_WU  = OF_CS + ROWS * 8 * 4;
    constexpr int OF_BUS = OF_WU + 64 * 8 * 4;

    extern __shared__ char sm[];
    char* AHI = sm;            char* ALO = sm + OF_ALO;
    char* RHI = sm + OF_RHI;   char* RLO = sm + OF_RLO;
    char* BHI = sm + OF_BHI;   char* BLO = sm + OF_BLO;
    float* cs  = (float*)(sm + OF_CS);
    float* wu  = (float*)(sm + OF_WU);
    float* bus = (float*)(sm + OF_BUS);

    const unsigned smb = smem_u32(sm);
    const unsigned uAHI = smb, uALO = smb + OF_ALO;
    const unsigned uRHI = smb + OF_RHI, uRLO = smb + OF_RLO;
    const unsigned uBHI = smb + OF_BHI, uBLO = smb + OF_BLO;

    const int t = threadIdx.x, lane = t & 31, w = t >> 5;
    const int wm = w >> 3, wn = w & 7, g = lane >> 2, tg = lane & 3;
    const int r0 = blockIdx.x * ROWS;

    // ---- phase 0a ----
    for (int idx = t; idx < ROWS * 7; idx += NTHR) {
        int i = idx / 7, f = idx % 7;
        cs[i * 8 + f] = contents[(size_t)(r0 + i) * 7 + f];
    }
    for (int idx = t; idx < 64 * 7; idx += NTHR) wu[(idx / 7) * 8 + (idx % 7)] = W_u[idx];
    if (t < 64) bus[t] = b_u[t];
    for (int idx = t; idx < ROWS * 32; idx += NTHR) {
        int i = idx >> 5, q = idx & 31, side = q >> 4, qq = q & 15;
        float4 v = *(const float4*)(up_prev + ((size_t)2 * (r0 + i) + side) * 64 + qq * 4);
        unsigned h0, l0, h1, l1;
        split_pack(v.x, v.y, h0, l0); split_pack(v.z, v.w, h1, l1);
        int col = 64 + side * 64 + qq * 4;
        *(uint2*)(AHI + i * SAB + col * 2) = make_uint2(h0, h1);
        *(uint2*)(ALO + i * SAB + col * 2) = make_uint2(l0, l1);
    }
    __syncthreads();
    // ---- phase 0b: u = relu(c @ W_u^T + b_u) -> cols 192..255; stage W_r chunk 0 ----
    for (int idx = t; idx < ROWS * 32; idx += NTHR) {
        int i = idx >> 5, cp = idx & 31;
        float a0 = bus[2 * cp], a1 = bus[2 * cp + 1];
#pragma unroll
        for (int f = 0; f < 7; f++) {
            float cv = cs[i * 8 + f];
            a0 = fmaf(cv, wu[(2 * cp) * 8 + f], a0);
            a1 = fmaf(cv, wu[(2 * cp + 1) * 8 + f], a1);
        }
        a0 = fmaxf(a0, 0.f); a1 = fmaxf(a1, 0.f);
        unsigned hi, lo; split_pack(a0, a1, hi, lo);
        *(unsigned*)(AHI + i * SAB + (192 + 2 * cp) * 2) = hi;
        *(unsigned*)(ALO + i * SAB + (192 + 2 * cp) * 2) = lo;
    }
    stageW(BHI, BLO, Wr_hi, Wr_lo, 0, 192, t);
    __syncthreads();

    // ---- GEMM1: rx = sigmoid(hhu @ W_r^T + b_r) * hhu, 3 chunks of N=64 ----
    for (int c = 0; c < 3; c++) {
        float acc[MT][4] = {};
        gemm_chunk<12, MT>(uAHI, uALO, SAB, 64, uBHI, uBLO, wm, wn, lane, acc);
        __syncthreads();
        if (c < 2) stageW(BHI, BLO, Wr_hi, Wr_lo, (c + 1) * 64, 192, t);
#pragma unroll
        for (int mt = 0; mt < MT; mt++)
#pragma unroll
            for (int rs = 0; rs < 2; rs++) {
                int row = (wm * MT + mt) * 16 + g + rs * 8;
                int o0 = c * 64 + wn * 8 + 2 * tg;
                float z0 = acc[mt][rs * 2 + 0] + __ldg(b_r + o0);
                float z1 = acc[mt][rs * 2 + 1] + __ldg(b_r + o0 + 1);
                float s0 = 1.f / (1.f + __expf(-z0));
                float s1 = 1.f / (1.f + __expf(-z1));
                float x0 = s0 * rd_split(AHI, ALO, row, 64 + o0, SAB);
                float x1 = s1 * rd_split(AHI, ALO, row, 64 + o0 + 1, SAB);
                unsigned hi, lo; split_pack(x0, x1, hi, lo);
                *(unsigned*)(RHI + row * SRB + o0 * 2) = hi;
                *(unsigned*)(RLO + row * SRB + o0 * 2) = lo;
            }
        __syncthreads();
    }

    // ---- GEMM2: h_H = relu(rx @ W_h^T + b_h) -> cols 0..63 ----
    stageW(BHI, BLO, Wh_hi, Wh_lo, 0, 192, t);
    __syncthreads();
    {
        float acc[MT][4] = {};
        gemm_chunk<12, MT>(uRHI, uRLO, SRB, 0, uBHI, uBLO, wm, wn, lane, acc);
#pragma unroll
        for (int mt = 0; mt < MT; mt++)
#pragma unroll
            for (int rs = 0; rs < 2; rs++) {
                int row = (wm * MT + mt) * 16 + g + rs * 8;
                int h0 = wn * 8 + 2 * tg;
                float v0 = fmaxf(acc[mt][rs * 2 + 0] + __ldg(b_h + h0), 0.f);
                float v1 = fmaxf(acc[mt][rs * 2 + 1] + __ldg(b_h + h0 + 1), 0.f);
                unsigned hi, lo; split_pack(v0, v1, hi, lo);
                *(unsigned*)(AHI + row * SAB + h0 * 2) = hi;
                *(unsigned*)(ALO + row * SAB + h0 * 2) = lo;
            }
    }
    __syncthreads();

    // ---- GEMM3: z = [h_H | hhu] @ W_z^T + b_z, 4 chunks (one per softmax group) ----
    float acc3[4][MT][4] = {};
    stageW(BHI, BLO, Wz_hi, Wz_lo, 0, 256, t);
    __syncthreads();
    for (int c = 0; c < 4; c++) {
        gemm_chunk<16, MT>(uAHI, uALO, SAB, 0, uBHI, uBLO, wm, wn, lane, acc3[c]);
        __syncthreads();
        if (c < 3) { stageW(BHI, BLO, Wz_hi, Wz_lo, (c + 1) * 64, 256, t); __syncthreads(); }
    }

    // ---- final: softmax over 4 groups, gated combine, store fp32 ----
#pragma unroll
    for (int mt = 0; mt < MT; mt++)
#pragma unroll
        for (int rs = 0; rs < 2; rs++) {
            int row = (wm * MT + mt) * 16 + g + rs * 8;
            int h0 = wn * 8 + 2 * tg;
            float res[2];
#pragma unroll
            for (int e = 0; e < 2; e++) {
                int h = h0 + e;
                float v0 = acc3[0][mt][rs * 2 + e] + __ldg(b_z + h);
                float v1 = acc3[1][mt][rs * 2 + e] + __ldg(b_z + 64 + h);
                float v2 = acc3[2][mt][rs * 2 + e] + __ldg(b_z + 128 + h);
                float v3 = acc3[3][mt][rs * 2 + e] + __ldg(b_z + 192 + h);
                float mx = fmaxf(fmaxf(v0, v1), fmaxf(v2, v3));
                float e0 = __expf(v0 - mx), e1 = __expf(v1 - mx);
                float e2 = __expf(v2 - mx), e3 = __expf(v3 - mx);
                float inv = 1.f / (e0 + e1 + e2 + e3);
                float hh = rd_split(AHI, ALO, row, h, SAB);
                float hl = rd_split(AHI, ALO, row, 64 + h, SAB);
                float hr = rd_split(AHI, ALO, row, 128 + h, SAB);
                float uu = rd_split(AHI, ALO, row, 192 + h, SAB);
                res[e] = (e0 * hh + e1 * hl + e2 * hr + e3 * uu) * inv;
            }
            *(float2*)(up_out + (size_t)(r0 + row) * 64 + h0) = make_float2(res[0], res[1]);
        }
}

static int smem_sz(int rows) {
    return rows * SAB * 2 + rows * SRB * 2 + 64 * SAB * 2 + rows * 8 * 4 + 64 * 8 * 4 + 256;
}

extern "C" void kernel_launch(void* const* d_in, const int* in_sizes, int n_in,
                              void* d_out, int out_size) {
    const float* contents = (const float*)d_in[0];
    const float* W_u = (const float*)d_in[1];
    const float* b_u = (const float*)d_in[2];
    const float* W_r = (const float*)d_in[3];
    const float* b_r = (const float*)d_in[4];
    const float* W_h = (const float*)d_in[5];
    const float* b_h = (const float*)d_in[6];
    const float* W_z = (const float*)d_in[7];
    const float* b_z = (const float*)d_in[8];
    float* out = (float*)d_out;

    float *upA = nullptr, *upB = nullptr;
    cudaGetSymbolAddress((void**)&upA, g_upA);
    cudaGetSymbolAddress((void**)&upB, g_upB);
    unsigned short *wrh, *wrl, *whh, *whl, *wzh, *wzl;
    cudaGetSymbolAddress((void**)&wrh, g_Wr_hi); cudaGetSymbolAddress((void**)&wrl, g_Wr_lo);
    cudaGetSymbolAddress((void**)&whh, g_Wh_hi); cudaGetSymbolAddress((void**)&whl, g_Wh_lo);
    cudaGetSymbolAddress((void**)&wzh, g_Wz_hi); cudaGetSymbolAddress((void**)&wzl, g_Wz_lo);

    const int smemBig = smem_sz(64), smemSmall = smem_sz(32);
    cudaFuncSetAttribute(grnn_level_kernel<64>,
                         cudaFuncAttributeMaxDynamicSharedMemorySize, smemBig);
    cudaFuncSetAttribute(grnn_level_kernel<32>,
                         cudaFuncAttributeMaxDynamicSharedMemorySize, smemSmall);

    prep_weights<<<(114688 + 255) / 256, 256>>>(W_r, W_h, W_z);

    // Level 12 (top): up = u
    {
        int n = 64 << 12;
        size_t off = (size_t)64 * ((1 << 12) - 1) * 7;
        int total = n * 64;
        grnn_top_kernel<<<(total + 255) / 256, 256>>>(contents + off, W_u, b_u, upA, n);
    }

    // Levels 11..0
    const float* prev = upA;
    for (int j = 11; j >= 0; j--) {
        int n = 64 << j;
        size_t off = (size_t)64 * ((1 << j) - 1) * 7;
        float* outp = (j == 0) ? out : ((j & 1) ? upB : upA);
        if (n >= 16384) {
            grnn_level_kernel<64><<<n / 64, NTHR, smemBig>>>(
                contents + off, prev, outp,
                W_u, b_u, wrh, wrl, b_r, whh, whl, b_h, wzh, wzl, b_z);
        } else {
            grnn_level_kernel<32><<<n / 32, NTHR, smemSmall>>>(
                contents + off, prev, outp,
                W_u, b_u, wrh, wrl, b_r, whh, whl, b_h, wzh, wzl, b_z);
        }
        prev = outp;
    }
}

// round 9
// speedup vs baseline: 2.3717x; 1.1844x over previous
#include <cuda_runtime.h>
#include <cuda_bf16.h>
#include <math.h>

// GRNNTransformGated via mma.sync.m16n8k16 bf16 (3-pass split ~ fp32 precision).
// K-outer GEMM structure: B staged as K-tiles (all N x 64k), A fragments loaded
// once per k-step and reused across all N-chunks. Weights pre-split in gmem.
// 512 threads (16 warps, 2m x 8n warp grid), ROWS=64 big levels / 32 small.

#define NTHR 512
#define SAB 528   // A buf row stride bytes; 528/4 % 32 = 4 -> ldmatrix conflict-free
#define SRB 400   // rx buf row stride bytes
#define SBB 144   // B k-tile row stride bytes (64k bf16 = 128B + pad); 144/4 % 32 = 4

__device__ float g_upA[262144 * 64];
__device__ float g_upB[131072 * 64];

// pre-split weights (bf16 hi/lo), [n][K] row-major
__device__ unsigned short g_Wr_hi[36864], g_Wr_lo[36864];
__device__ unsigned short g_Wh_hi[12288], g_Wh_lo[12288];
__device__ unsigned short g_Wz_hi[65536], g_Wz_lo[65536];

__device__ __forceinline__ void split_pack(float a, float b, unsigned& hi, unsigned& lo) {
    __nv_bfloat16 ha = __float2bfloat16(a), hb = __float2bfloat16(b);
    __nv_bfloat16 la = __float2bfloat16(a - __bfloat162float(ha));
    __nv_bfloat16 lb = __float2bfloat16(b - __bfloat162float(hb));
    hi = (unsigned)__bfloat16_as_ushort(ha) | ((unsigned)__bfloat16_as_ushort(hb) << 16);
    lo = (unsigned)__bfloat16_as_ushort(la) | ((unsigned)__bfloat16_as_ushort(lb) << 16);
}
__device__ __forceinline__ float rd_split(const char* hi, const char* lo, int row, int col, int strideB) {
    return __bfloat162float(*(const __nv_bfloat16*)(hi + row * strideB + col * 2)) +
           __bfloat162float(*(const __nv_bfloat16*)(lo + row * strideB + col * 2));
}
__device__ __forceinline__ unsigned smem_u32(const void* p) {
    unsigned a;
    asm("{ .reg .u64 t; cvta.to.shared.u64 t, %1; cvt.u32.u64 %0, t; }" : "=r"(a) : "l"(p));
    return a;
}
__device__ __forceinline__ void mma16816(float* c, const unsigned* a, const unsigned* b) {
    asm volatile("mma.sync.aligned.m16n8k16.row.col.f32.bf16.bf16.f32 "
                 "{%0,%1,%2,%3}, {%4,%5,%6,%7}, {%8,%9}, {%0,%1,%2,%3};"
                 : "+f"(c[0]), "+f"(c[1]), "+f"(c[2]), "+f"(c[3])
                 : "r"(a[0]), "r"(a[1]), "r"(a[2]), "r"(a[3]), "r"(b[0]), "r"(b[1]));
}
#define LDSM_X4(d, addr) \
    asm volatile("ldmatrix.sync.aligned.m8n8.x4.shared.b16 {%0,%1,%2,%3}, [%4];" \
                 : "=r"((d)[0]), "=r"((d)[1]), "=r"((d)[2]), "=r"((d)[3]) : "r"(addr))
#define LDSM_X2(d, addr) \
    asm volatile("ldmatrix.sync.aligned.m8n8.x2.shared.b16 {%0,%1}, [%2];" \
                 : "=r"((d)[0]), "=r"((d)[1]) : "r"(addr))

// ---------------- weight prep: fp32 -> bf16 hi/lo (once per launch) ----------------
__global__ void prep_weights(const float* __restrict__ W_r,
                             const float* __restrict__ W_h,
                             const float* __restrict__ W_z) {
    int i = blockIdx.x * blockDim.x + threadIdx.x;
    float v; unsigned short* ph; unsigned short* pl; int k;
    if (i < 36864)       { v = W_r[i];            ph = g_Wr_hi; pl = g_Wr_lo; k = i; }
    else if (i < 49152)  { v = W_h[i - 36864];    ph = g_Wh_hi; pl = g_Wh_lo; k = i - 36864; }
    else if (i < 114688) { v = W_z[i - 49152];    ph = g_Wz_hi; pl = g_Wz_lo; k = i - 49152; }
    else return;
    __nv_bfloat16 h = __float2bfloat16(v);
    __nv_bfloat16 l = __float2bfloat16(v - __bfloat162float(h));
    ph[k] = __bfloat16_as_ushort(h);
    pl[k] = __bfloat16_as_ushort(l);
}

// stage NR rows x 64 k (bf16 pre-split, src row-major [NR][Ksrc] at k0) into B tile
__device__ __forceinline__ void stage_tile(char* BHI, char* BLO,
                                           const unsigned short* __restrict__ Whi,
                                           const unsigned short* __restrict__ Wlo,
                                           int NR, int Ksrc, int k0, int t) {
    for (int e = t; e < NR * 8; e += NTHR) {
        int n = e >> 3, kq = (e & 7) * 8;
        *(uint4*)(BHI + n * SBB + kq * 2) = *(const uint4*)(Whi + (size_t)n * Ksrc + k0 + kq);
        *(uint4*)(BLO + n * SBB + kq * 2) = *(const uint4*)(Wlo + (size_t)n * Ksrc + k0 + kq);
    }
}

// ---------------- top level (j=12) ----------------
__global__ void grnn_top_kernel(const float* __restrict__ contents,
                                const float* __restrict__ W_u,
                                const float* __restrict__ b_u,
                                float* __restrict__ up, int n) {
    int idx = blockIdx.x * blockDim.x + threadIdx.x;
    if (idx >= n * 64) return;
    int i = idx >> 6, h = idx & 63;
    const float* c = contents + (size_t)i * 7;
    const float* w = W_u + h * 7;
    float acc = b_u[h];
#pragma unroll
    for (int f = 0; f < 7; f++) acc = fmaf(__ldg(c + f), __ldg(w + f), acc);
    up[idx] = fmaxf(acc, 0.f);
}

// ---------------- fused level kernel: ROWS rows / block, 512 threads ----------------
template <int ROWS>
__global__ __launch_bounds__(NTHR, 1) void grnn_level_kernel(
    const float* __restrict__ contents,
    const float* __restrict__ up_prev,
    float* __restrict__ up_out,
    const float* __restrict__ W_u, const float* __restrict__ b_u,
    const unsigned short* __restrict__ Wr_hi, const unsigned short* __restrict__ Wr_lo,
    const float* __restrict__ b_r,
    const unsigned short* __restrict__ Wh_hi, const unsigned short* __restrict__ Wh_lo,
    const float* __restrict__ b_h,
    const unsigned short* __restrict__ Wz_hi, const unsigned short* __restrict__ Wz_lo,
    const float* __restrict__ b_z)
{
    constexpr int MT = ROWS / 32;
    constexpr int OF_ALO = ROWS * SAB;
    constexpr int OF_RHI = OF_ALO + ROWS * SAB;
    constexpr int OF_RLO = OF_RHI + ROWS * SRB;
    constexpr int OF_BHI = OF_RLO + ROWS * SRB;
    constexpr int OF_BLO = OF_BHI + 256 * SBB;
    constexpr int OF_CS  = OF_BLO + 256 * SBB;
    constexpr int OF_WU  = OF_CS + ROWS * 8 * 4;
    constexpr int OF_BUS = OF_WU + 64 * 8 * 4;

    extern __shared__ char sm[];
    char* AHI = sm;            char* ALO = sm + OF_ALO;
    char* RHI = sm + OF_RHI;   char* RLO = sm + OF_RLO;
    char* BHI = sm + OF_BHI;   char* BLO = sm + OF_BLO;
    float* cs  = (float*)(sm + OF_CS);
    float* wu  = (float*)(sm + OF_WU);
    float* bus = (float*)(sm + OF_BUS);

    const unsigned smb = smem_u32(sm);
    const unsigned uAHI = smb, uALO = smb + OF_ALO;
    const unsigned uRHI = smb + OF_RHI, uRLO = smb + OF_RLO;
    const unsigned uBHI = smb + OF_BHI, uBLO = smb + OF_BLO;

    const int t = threadIdx.x, lane = t & 31, w = t >> 5;
    const int wm = w >> 3, wn = w & 7, g = lane >> 2, tg = lane & 3;
    const int l16 = lane & 15;
    const unsigned aSel = ((lane >> 4) & 1) * 16;
    const unsigned bSel = ((lane >> 3) & 1) * 16;
    const int r0 = blockIdx.x * ROWS;

    // ---- phase 0a ----
    for (int idx = t; idx < ROWS * 7; idx += NTHR) {
        int i = idx / 7, f = idx % 7;
        cs[i * 8 + f] = contents[(size_t)(r0 + i) * 7 + f];
    }
    for (int idx = t; idx < 64 * 7; idx += NTHR) wu[(idx / 7) * 8 + (idx % 7)] = W_u[idx];
    if (t < 64) bus[t] = b_u[t];
    for (int idx = t; idx < ROWS * 32; idx += NTHR) {
        int i = idx >> 5, q = idx & 31, side = q >> 4, qq = q & 15;
        float4 v = *(const float4*)(up_prev + ((size_t)2 * (r0 + i) + side) * 64 + qq * 4);
        unsigned h0, l0, h1, l1;
        split_pack(v.x, v.y, h0, l0); split_pack(v.z, v.w, h1, l1);
        int col = 64 + side * 64 + qq * 4;
        *(uint2*)(AHI + i * SAB + col * 2) = make_uint2(h0, h1);
        *(uint2*)(ALO + i * SAB + col * 2) = make_uint2(l0, l1);
    }
    __syncthreads();
    // ---- phase 0b: u = relu(c @ W_u^T + b_u) -> cols 192..255 ----
    for (int idx = t; idx < ROWS * 32; idx += NTHR) {
        int i = idx >> 5, cp = idx & 31;
        float a0 = bus[2 * cp], a1 = bus[2 * cp + 1];
#pragma unroll
        for (int f = 0; f < 7; f++) {
            float cv = cs[i * 8 + f];
            a0 = fmaf(cv, wu[(2 * cp) * 8 + f], a0);
            a1 = fmaf(cv, wu[(2 * cp + 1) * 8 + f], a1);
        }
        a0 = fmaxf(a0, 0.f); a1 = fmaxf(a1, 0.f);
        unsigned hi, lo; split_pack(a0, a1, hi, lo);
        *(unsigned*)(AHI + i * SAB + (192 + 2 * cp) * 2) = hi;
        *(unsigned*)(ALO + i * SAB + (192 + 2 * cp) * 2) = lo;
    }

    // ---- GEMM1: rx = sigmoid(hhu @ W_r^T + b_r) * hhu; K-outer, 3 N-chunks ----
    float acc1[3][MT][4] = {};
    for (int kc = 0; kc < 3; kc++) {
        if (kc > 0) __syncthreads();           // prior B reads done before restage
        stage_tile(BHI, BLO, Wr_hi, Wr_lo, 192, 192, kc * 64, t);
        __syncthreads();
#pragma unroll
        for (int kk = 0; kk < 4; kk++) {
            unsigned ah[MT][4], al[MT][4];
#pragma unroll
            for (int mt = 0; mt < MT; mt++) {
                unsigned off = (unsigned)(((wm * MT + mt) * 16 + l16) * SAB
                                          + (64 + kc * 64 + kk * 16) * 2) + aSel;
                LDSM_X4(ah[mt], uAHI + off);
                LDSM_X4(al[mt], uALO + off);
            }
#pragma unroll
            for (int c = 0; c < 3; c++) {
                unsigned bo = (unsigned)((c * 64 + wn * 8 + (lane & 7)) * SBB + kk * 32) + bSel;
                unsigned bh[2], bl[2];
                LDSM_X2(bh, uBHI + bo);
                LDSM_X2(bl, uBLO + bo);
#pragma unroll
                for (int mt = 0; mt < MT; mt++) {
                    mma16816(acc1[c][mt], ah[mt], bh);
                    mma16816(acc1[c][mt], ah[mt], bl);
                    mma16816(acc1[c][mt], al[mt], bh);
                }
            }
        }
    }
    __syncthreads();
    // epilogue 1 + stage W_h (3 k-tiles stacked as virtual rows)
#pragma unroll
    for (int c = 0; c < 3; c++)
#pragma unroll
        for (int mt = 0; mt < MT; mt++)
#pragma unroll
            for (int rs = 0; rs < 2; rs++) {
                int row = (wm * MT + mt) * 16 + g + rs * 8;
                int o0 = c * 64 + wn * 8 + 2 * tg;
                float z0 = acc1[c][mt][rs * 2 + 0] + __ldg(b_r + o0);
                float z1 = acc1[c][mt][rs * 2 + 1] + __ldg(b_r + o0 + 1);
                float s0 = 1.f / (1.f + __expf(-z0));
                float s1 = 1.f / (1.f + __expf(-z1));
                float x0 = s0 * rd_split(AHI, ALO, row, 64 + o0, SAB);
                float x1 = s1 * rd_split(AHI, ALO, row, 64 + o0 + 1, SAB);
                unsigned hi, lo; split_pack(x0, x1, hi, lo);
                *(unsigned*)(RHI + row * SRB + o0 * 2) = hi;
                *(unsigned*)(RLO + row * SRB + o0 * 2) = lo;
            }
    for (int kt = 0; kt < 3; kt++)
        stage_tile(BHI + kt * 64 * SBB, BLO + kt * 64 * SBB, Wh_hi, Wh_lo, 64, 192, kt * 64, t);
    __syncthreads();

    // ---- GEMM2: h_H = relu(rx @ W_h^T + b_h) -> AHI cols 0..63 ----
    {
        float acc[MT][4] = {};
#pragma unroll
        for (int kk = 0; kk < 12; kk++) {
            int kt = kk >> 2, k2 = kk & 3;
            unsigned ah[MT][4], al[MT][4];
#pragma unroll
            for (int mt = 0; mt < MT; mt++) {
                unsigned off = (unsigned)(((wm * MT + mt) * 16 + l16) * SRB + kk * 32) + aSel;
                LDSM_X4(ah[mt], uRHI + off);
                LDSM_X4(al[mt], uRLO + off);
            }
            unsigned bo = (unsigned)((kt * 64 + wn * 8 + (lane & 7)) * SBB + k2 * 32) + bSel;
            unsigned bh[2], bl[2];
            LDSM_X2(bh, uBHI + bo);
            LDSM_X2(bl, uBLO + bo);
#pragma unroll
            for (int mt = 0; mt < MT; mt++) {
                mma16816(acc[mt], ah[mt], bh);
                mma16816(acc[mt], ah[mt], bl);
                mma16816(acc[mt], al[mt], bh);
            }
        }
#pragma unroll
        for (int mt = 0; mt < MT; mt++)
#pragma unroll
            for (int rs = 0; rs < 2; rs++) {
                int row = (wm * MT + mt) * 16 + g + rs * 8;
                int h0 = wn * 8 + 2 * tg;
                float v0 = fmaxf(acc[mt][rs * 2 + 0] + __ldg(b_h + h0), 0.f);
                float v1 = fmaxf(acc[mt][rs * 2 + 1] + __ldg(b_h + h0 + 1), 0.f);
                unsigned hi, lo; split_pack(v0, v1, hi, lo);
                *(unsigned*)(AHI + row * SAB + h0 * 2) = hi;
                *(unsigned*)(ALO + row * SAB + h0 * 2) = lo;
            }
    }
    __syncthreads();

    // ---- GEMM3: z = [h_H | hhu] @ W_z^T + b_z; K-outer, 4 N-chunks ----
    float acc3[4][MT][4] = {};
    for (int kc = 0; kc < 4; kc++) {
        if (kc > 0) __syncthreads();
        stage_tile(BHI, BLO, Wz_hi, Wz_lo, 256, 256, kc * 64, t);
        __syncthreads();
#pragma unroll
        for (int kk = 0; kk < 4; kk++) {
            unsigned ah[MT][4], al[MT][4];
#pragma unroll
            for (int mt = 0; mt < MT; mt++) {
                unsigned off = (unsigned)(((wm * MT + mt) * 16 + l16) * SAB
                                          + (kc * 64 + kk * 16) * 2) + aSel;
                LDSM_X4(ah[mt], uAHI + off);
                LDSM_X4(al[mt], uALO + off);
            }
#pragma unroll
            for (int c = 0; c < 4; c++) {
                unsigned bo = (unsigned)((c * 64 + wn * 8 + (lane & 7)) * SBB + kk * 32) + bSel;
                unsigned bh[2], bl[2];
                LDSM_X2(bh, uBHI + bo);
                LDSM_X2(bl, uBLO + bo);
#pragma unroll
                for (int mt = 0; mt < MT; mt++) {
                    mma16816(acc3[c][mt], ah[mt], bh);
                    mma16816(acc3[c][mt], ah[mt], bl);
                    mma16816(acc3[c][mt], al[mt], bh);
                }
            }
        }
    }

    // ---- final: softmax over 4 groups, gated combine, store fp32 ----
#pragma unroll
    for (int mt = 0; mt < MT; mt++)
#pragma unroll
        for (int rs = 0; rs < 2; rs++) {
            int row = (wm * MT + mt) * 16 + g + rs * 8;
            int h0 = wn * 8 + 2 * tg;
            float res[2];
#pragma unroll
            for (int e = 0; e < 2; e++) {
                int h = h0 + e;
                float v0 = acc3[0][mt][rs * 2 + e] + __ldg(b_z + h);
                float v1 = acc3[1][mt][rs * 2 + e] + __ldg(b_z + 64 + h);
                float v2 = acc3[2][mt][rs * 2 + e] + __ldg(b_z + 128 + h);
                float v3 = acc3[3][mt][rs * 2 + e] + __ldg(b_z + 192 + h);
                float mx = fmaxf(fmaxf(v0, v1), fmaxf(v2, v3));
                float e0 = __expf(v0 - mx), e1 = __expf(v1 - mx);
                float e2 = __expf(v2 - mx), e3 = __expf(v3 - mx);
                float inv = 1.f / (e0 + e1 + e2 + e3);
                float hh = rd_split(AHI, ALO, row, h, SAB);
                float hl = rd_split(AHI, ALO, row, 64 + h, SAB);
                float hr = rd_split(AHI, ALO, row, 128 + h, SAB);
                float uu = rd_split(AHI, ALO, row, 192 + h, SAB);
                res[e] = (e0 * hh + e1 * hl + e2 * hr + e3 * uu) * inv;
            }
            *(float2*)(up_out + (size_t)(r0 + row) * 64 + h0) = make_float2(res[0], res[1]);
        }
}

static int smem_sz(int rows) {
    return rows * SAB * 2 + rows * SRB * 2 + 256 * SBB * 2 + rows * 8 * 4 + 64 * 8 * 4 + 256;
}

extern "C" void kernel_launch(void* const* d_in, const int* in_sizes, int n_in,
                              void* d_out, int out_size) {
    const float* contents = (const float*)d_in[0];
    const float* W_u = (const float*)d_in[1];
    const float* b_u = (const float*)d_in[2];
    const float* W_r = (const float*)d_in[3];
    const float* b_r = (const float*)d_in[4];
    const float* W_h = (const float*)d_in[5];
    const float* b_h = (const float*)d_in[6];
    const float* W_z = (const float*)d_in[7];
    const float* b_z = (const float*)d_in[8];
    float* out = (float*)d_out;

    float *upA = nullptr, *upB = nullptr;
    cudaGetSymbolAddress((void**)&upA, g_upA);
    cudaGetSymbolAddress((void**)&upB, g_upB);
    unsigned short *wrh, *wrl, *whh, *whl, *wzh, *wzl;
    cudaGetSymbolAddress((void**)&wrh, g_Wr_hi); cudaGetSymbolAddress((void**)&wrl, g_Wr_lo);
    cudaGetSymbolAddress((void**)&whh, g_Wh_hi); cudaGetSymbolAddress((void**)&whl, g_Wh_lo);
    cudaGetSymbolAddress((void**)&wzh, g_Wz_hi); cudaGetSymbolAddress((void**)&wzl, g_Wz_lo);

    const int smemBig = smem_sz(64), smemSmall = smem_sz(32);
    cudaFuncSetAttribute(grnn_level_kernel<64>,
                         cudaFuncAttributeMaxDynamicSharedMemorySize, smemBig);
    cudaFuncSetAttribute(grnn_level_kernel<32>,
                         cudaFuncAttributeMaxDynamicSharedMemorySize, smemSmall);

    prep_weights<<<(114688 + 255) / 256, 256>>>(W_r, W_h, W_z);

    // Level 12 (top): up = u
    {
        int n = 64 << 12;
        size_t off = (size_t)64 * ((1 << 12) - 1) * 7;
        int total = n * 64;
        grnn_top_kernel<<<(total + 255) / 256, 256>>>(contents + off, W_u, b_u, upA, n);
    }

    // Levels 11..0
    const float* prev = upA;
    for (int j = 11; j >= 0; j--) {
        int n = 64 << j;
        size_t off = (size_t)64 * ((1 << j) - 1) * 7;
        float* outp = (j == 0) ? out : ((j & 1) ? upB : upA);
        if (n >= 16384) {
            grnn_level_kernel<64><<<n / 64, NTHR, smemBig>>>(
                contents + off, prev, outp,
                W_u, b_u, wrh, wrl, b_r, whh, whl, b_h, wzh, wzl, b_z);
        } else {
            grnn_level_kernel<32><<<n / 32, NTHR, smemSmall>>>(
                contents + off, prev, outp,
                W_u, b_u, wrh, wrl, b_r, whh, whl, b_h, wzh, wzl, b_z);
        }
        prev = outp;
    }
}

// round 10
// speedup vs baseline: 2.4230x; 1.0216x over previous
#include <cuda_runtime.h>
#include <cuda_bf16.h>
#include <math.h>

// GRNNTransformGated via mma.sync.m16n8k16 bf16 (3-pass split ~ fp32 precision).
// K-outer GEMMs, pre-split weights, ldmatrix fragments.
// NT=1024 (32 warps, 4m x 8n, MT=1) big levels; NT=512 (2m x 8n) small levels.

#define SAB 528   // A buf row stride bytes; (528/4)%32=4 -> ldmatrix conflict-free
#define SRB 400   // rx buf row stride bytes; (400/4)%32=4
#define SBB 144   // B k-tile row stride bytes; (144/4)%32=4

__device__ float g_upA[262144 * 64];
__device__ float g_upB[131072 * 64];

// pre-split weights (bf16 hi/lo), [n][K] row-major
__device__ unsigned short g_Wr_hi[36864], g_Wr_lo[36864];
__device__ unsigned short g_Wh_hi[12288], g_Wh_lo[12288];
__device__ unsigned short g_Wz_hi[65536], g_Wz_lo[65536];

__device__ __forceinline__ void split_pack(float a, float b, unsigned& hi, unsigned& lo) {
    __nv_bfloat16 ha = __float2bfloat16(a), hb = __float2bfloat16(b);
    __nv_bfloat16 la = __float2bfloat16(a - __bfloat162float(ha));
    __nv_bfloat16 lb = __float2bfloat16(b - __bfloat162float(hb));
    hi = (unsigned)__bfloat16_as_ushort(ha) | ((unsigned)__bfloat16_as_ushort(hb) << 16);
    lo = (unsigned)__bfloat16_as_ushort(la) | ((unsigned)__bfloat16_as_ushort(lb) << 16);
}
__device__ __forceinline__ float rd_split(const char* hi, const char* lo, int row, int col, int strideB) {
    return __bfloat162float(*(const __nv_bfloat16*)(hi + row * strideB + col * 2)) +
           __bfloat162float(*(const __nv_bfloat16*)(lo + row * strideB + col * 2));
}
__device__ __forceinline__ unsigned smem_u32(const void* p) {
    unsigned a;
    asm("{ .reg .u64 t; cvta.to.shared.u64 t, %1; cvt.u32.u64 %0, t; }" : "=r"(a) : "l"(p));
    return a;
}
__device__ __forceinline__ void mma16816(float* c, const unsigned* a, const unsigned* b) {
    asm volatile("mma.sync.aligned.m16n8k16.row.col.f32.bf16.bf16.f32 "
                 "{%0,%1,%2,%3}, {%4,%5,%6,%7}, {%8,%9}, {%0,%1,%2,%3};"
                 : "+f"(c[0]), "+f"(c[1]), "+f"(c[2]), "+f"(c[3])
                 : "r"(a[0]), "r"(a[1]), "r"(a[2]), "r"(a[3]), "r"(b[0]), "r"(b[1]));
}
#define LDSM_X4(d, addr) \
    asm volatile("ldmatrix.sync.aligned.m8n8.x4.shared.b16 {%0,%1,%2,%3}, [%4];" \
                 : "=r"((d)[0]), "=r"((d)[1]), "=r"((d)[2]), "=r"((d)[3]) : "r"(addr))
#define LDSM_X2(d, addr) \
    asm volatile("ldmatrix.sync.aligned.m8n8.x2.shared.b16 {%0,%1}, [%2];" \
                 : "=r"((d)[0]), "=r"((d)[1]) : "r"(addr))

// ---------------- weight prep: fp32 -> bf16 hi/lo (once per launch) ----------------
__global__ void prep_weights(const float* __restrict__ W_r,
                             const float* __restrict__ W_h,
                             const float* __restrict__ W_z) {
    int i = blockIdx.x * blockDim.x + threadIdx.x;
    float v; unsigned short* ph; unsigned short* pl; int k;
    if (i < 36864)       { v = W_r[i];            ph = g_Wr_hi; pl = g_Wr_lo; k = i; }
    else if (i < 49152)  { v = W_h[i - 36864];    ph = g_Wh_hi; pl = g_Wh_lo; k = i - 36864; }
    else if (i < 114688) { v = W_z[i - 49152];    ph = g_Wz_hi; pl = g_Wz_lo; k = i - 49152; }
    else return;
    __nv_bfloat16 h = __float2bfloat16(v);
    __nv_bfloat16 l = __float2bfloat16(v - __bfloat162float(h));
    ph[k] = __bfloat16_as_ushort(h);
    pl[k] = __bfloat16_as_ushort(l);
}

// stage NR rows x 64 k (bf16 pre-split, src row-major [NR][Ksrc] at k0) into B tile
template <int NT>
__device__ __forceinline__ void stage_tile(char* BHI, char* BLO,
                                           const unsigned short* __restrict__ Whi,
                                           const unsigned short* __restrict__ Wlo,
                                           int NR, int Ksrc, int k0, int t) {
    for (int e = t; e < NR * 8; e += NT) {
        int n = e >> 3, kq = (e & 7) * 8;
        *(uint4*)(BHI + n * SBB + kq * 2) = *(const uint4*)(Whi + (size_t)n * Ksrc + k0 + kq);
        *(uint4*)(BLO + n * SBB + kq * 2) = *(const uint4*)(Wlo + (size_t)n * Ksrc + k0 + kq);
    }
}

// ---------------- top level (j=12) ----------------
__global__ void grnn_top_kernel(const float* __restrict__ contents,
                                const float* __restrict__ W_u,
                                const float* __restrict__ b_u,
                                float* __restrict__ up, int n) {
    int idx = blockIdx.x * blockDim.x + threadIdx.x;
    if (idx >= n * 64) return;
    int i = idx >> 6, h = idx & 63;
    const float* c = contents + (size_t)i * 7;
    const float* w = W_u + h * 7;
    float acc = b_u[h];
#pragma unroll
    for (int f = 0; f < 7; f++) acc = fmaf(__ldg(c + f), __ldg(w + f), acc);
    up[idx] = fmaxf(acc, 0.f);
}

// ---------------- fused level kernel: ROWS = NT/16 rows, MT=1 per warp ----------------
template <int NT>
__global__ __launch_bounds__(NT, 1) void grnn_level_kernel(
    const float* __restrict__ contents,
    const float* __restrict__ up_prev,
    float* __restrict__ up_out,
    const float* __restrict__ W_u, const float* __restrict__ b_u,
    const unsigned short* __restrict__ Wr_hi, const unsigned short* __restrict__ Wr_lo,
    const float* __restrict__ b_r,
    const unsigned short* __restrict__ Wh_hi, const unsigned short* __restrict__ Wh_lo,
    const float* __restrict__ b_h,
    const unsigned short* __restrict__ Wz_hi, const unsigned short* __restrict__ Wz_lo,
    const float* __restrict__ b_z)
{
    constexpr int ROWS = (NT / 256) * 16;   // 1024 -> 64, 512 -> 32
    constexpr int OF_ALO = ROWS * SAB;
    constexpr int OF_RHI = OF_ALO + ROWS * SAB;
    constexpr int OF_RLO = OF_RHI + ROWS * SRB;
    constexpr int OF_BHI = OF_RLO + ROWS * SRB;
    constexpr int OF_BLO = OF_BHI + 256 * SBB;
    constexpr int OF_CS  = OF_BLO + 256 * SBB;
    constexpr int OF_WU  = OF_CS + ROWS * 8 * 4;
    constexpr int OF_BUS = OF_WU + 64 * 8 * 4;

    extern __shared__ char sm[];
    char* AHI = sm;            char* ALO = sm + OF_ALO;
    char* RHI = sm + OF_RHI;   char* RLO = sm + OF_RLO;
    char* BHI = sm + OF_BHI;   char* BLO = sm + OF_BLO;
    float* cs  = (float*)(sm + OF_CS);
    float* wu  = (float*)(sm + OF_WU);
    float* bus = (float*)(sm + OF_BUS);

    const unsigned smb = smem_u32(sm);
    const unsigned uAHI = smb, uALO = smb + OF_ALO;
    const unsigned uRHI = smb + OF_RHI, uRLO = smb + OF_RLO;
    const unsigned uBHI = smb + OF_BHI, uBLO = smb + OF_BLO;

    const int t = threadIdx.x, lane = t & 31, w = t >> 5;
    const int wm = w >> 3, wn = w & 7, g = lane >> 2, tg = lane & 3;
    const int l16 = lane & 15;
    const unsigned aSel = ((lane >> 4) & 1) * 16;
    const unsigned bSel = ((lane >> 3) & 1) * 16;
    const int r0 = blockIdx.x * ROWS;
    const int arow = wm * 16 + l16;           // this warp's A fragment row

    // ---- phase 0a ----
    for (int idx = t; idx < ROWS * 7; idx += NT) {
        int i = idx / 7, f = idx % 7;
        cs[i * 8 + f] = contents[(size_t)(r0 + i) * 7 + f];
    }
    for (int idx = t; idx < 64 * 7; idx += NT) wu[(idx / 7) * 8 + (idx % 7)] = W_u[idx];
    if (t < 64) bus[t] = b_u[t];
    for (int idx = t; idx < ROWS * 32; idx += NT) {
        int i = idx >> 5, q = idx & 31, side = q >> 4, qq = q & 15;
        float4 v = *(const float4*)(up_prev + ((size_t)2 * (r0 + i) + side) * 64 + qq * 4);
        unsigned h0, l0, h1, l1;
        split_pack(v.x, v.y, h0, l0); split_pack(v.z, v.w, h1, l1);
        int col = 64 + side * 64 + qq * 4;
        *(uint2*)(AHI + i * SAB + col * 2) = make_uint2(h0, h1);
        *(uint2*)(ALO + i * SAB + col * 2) = make_uint2(l0, l1);
    }
    __syncthreads();
    // ---- phase 0b: u = relu(c @ W_u^T + b_u) -> cols 192..255 ----
    for (int idx = t; idx < ROWS * 32; idx += NT) {
        int i = idx >> 5, cp = idx & 31;
        float a0 = bus[2 * cp], a1 = bus[2 * cp + 1];
#pragma unroll
        for (int f = 0; f < 7; f++) {
            float cv = cs[i * 8 + f];
            a0 = fmaf(cv, wu[(2 * cp) * 8 + f], a0);
            a1 = fmaf(cv, wu[(2 * cp + 1) * 8 + f], a1);
        }
        a0 = fmaxf(a0, 0.f); a1 = fmaxf(a1, 0.f);
        unsigned hi, lo; split_pack(a0, a1, hi, lo);
        *(unsigned*)(AHI + i * SAB + (192 + 2 * cp) * 2) = hi;
        *(unsigned*)(ALO + i * SAB + (192 + 2 * cp) * 2) = lo;
    }

    // ---- GEMM1: rx = sigmoid(hhu @ W_r^T + b_r) * hhu; K-outer, 3 N-chunks ----
    float acc1[3][4] = {};
    for (int kc = 0; kc < 3; kc++) {
        if (kc > 0) __syncthreads();
        stage_tile<NT>(BHI, BLO, Wr_hi, Wr_lo, 192, 192, kc * 64, t);
        __syncthreads();
#pragma unroll
        for (int kk = 0; kk < 4; kk++) {
            unsigned ah[4], al[4];
            unsigned off = (unsigned)(arow * SAB + (64 + kc * 64 + kk * 16) * 2) + aSel;
            LDSM_X4(ah, uAHI + off);
            LDSM_X4(al, uALO + off);
#pragma unroll
            for (int c = 0; c < 3; c++) {
                unsigned bo = (unsigned)((c * 64 + wn * 8 + (lane & 7)) * SBB + kk * 32) + bSel;
                unsigned bh[2], bl[2];
                LDSM_X2(bh, uBHI + bo);
                LDSM_X2(bl, uBLO + bo);
                mma16816(acc1[c], ah, bh);
                mma16816(acc1[c], ah, bl);
                mma16816(acc1[c], al, bh);
            }
        }
    }
    __syncthreads();
    // epilogue 1 + stage W_h (3 k-tiles stacked as virtual rows)
#pragma unroll
    for (int c = 0; c < 3; c++)
#pragma unroll
        for (int rs = 0; rs < 2; rs++) {
            int row = wm * 16 + g + rs * 8;
            int o0 = c * 64 + wn * 8 + 2 * tg;
            float z0 = acc1[c][rs * 2 + 0] + __ldg(b_r + o0);
            float z1 = acc1[c][rs * 2 + 1] + __ldg(b_r + o0 + 1);
            float s0 = 1.f / (1.f + __expf(-z0));
            float s1 = 1.f / (1.f + __expf(-z1));
            float x0 = s0 * rd_split(AHI, ALO, row, 64 + o0, SAB);
            float x1 = s1 * rd_split(AHI, ALO, row, 64 + o0 + 1, SAB);
            unsigned hi, lo; split_pack(x0, x1, hi, lo);
            *(unsigned*)(RHI + row * SRB + o0 * 2) = hi;
            *(unsigned*)(RLO + row * SRB + o0 * 2) = lo;
        }
    for (int kt = 0; kt < 3; kt++)
        stage_tile<NT>(BHI + kt * 64 * SBB, BLO + kt * 64 * SBB, Wh_hi, Wh_lo, 64, 192, kt * 64, t);
    __syncthreads();

    // ---- GEMM2: h_H = relu(rx @ W_h^T + b_h) -> AHI cols 0..63 ----
    {
        float acc[4] = {};
#pragma unroll
        for (int kk = 0; kk < 12; kk++) {
            int kt = kk >> 2, k2 = kk & 3;
            unsigned ah[4], al[4];
            unsigned off = (unsigned)(arow * SRB + kk * 32) + aSel;
            LDSM_X4(ah, uRHI + off);
            LDSM_X4(al, uRLO + off);
            unsigned bo = (unsigned)((kt * 64 + wn * 8 + (lane & 7)) * SBB + k2 * 32) + bSel;
            unsigned bh[2], bl[2];
            LDSM_X2(bh, uBHI + bo);
            LDSM_X2(bl, uBLO + bo);
            mma16816(acc, ah, bh);
            mma16816(acc, ah, bl);
            mma16816(acc, al, bh);
        }
#pragma unroll
        for (int rs = 0; rs < 2; rs++) {
            int row = wm * 16 + g + rs * 8;
            int h0 = wn * 8 + 2 * tg;
            float v0 = fmaxf(acc[rs * 2 + 0] + __ldg(b_h + h0), 0.f);
            float v1 = fmaxf(acc[rs * 2 + 1] + __ldg(b_h + h0 + 1), 0.f);
            unsigned hi, lo; split_pack(v0, v1, hi, lo);
            *(unsigned*)(AHI + row * SAB + h0 * 2) = hi;
            *(unsigned*)(ALO + row * SAB + h0 * 2) = lo;
        }
    }
    __syncthreads();

    // ---- GEMM3: z = [h_H | hhu] @ W_z^T + b_z; K-outer, 4 N-chunks ----
    float acc3[4][4] = {};
    for (int kc = 0; kc < 4; kc++) {
        if (kc > 0) __syncthreads();
        stage_tile<NT>(BHI, BLO, Wz_hi, Wz_lo, 256, 256, kc * 64, t);
        __syncthreads();
#pragma unroll
        for (int kk = 0; kk < 4; kk++) {
            unsigned ah[4], al[4];
            unsigned off = (unsigned)(arow * SAB + (kc * 64 + kk * 16) * 2) + aSel;
            LDSM_X4(ah, uAHI + off);
            LDSM_X4(al, uALO + off);
#pragma unroll
            for (int c = 0; c < 4; c++) {
                unsigned bo = (unsigned)((c * 64 + wn * 8 + (lane & 7)) * SBB + kk * 32) + bSel;
                unsigned bh[2], bl[2];
                LDSM_X2(bh, uBHI + bo);
                LDSM_X2(bl, uBLO + bo);
                mma16816(acc3[c], ah, bh);
                mma16816(acc3[c], ah, bl);
                mma16816(acc3[c], al, bh);
            }
        }
    }

    // ---- final: softmax over 4 groups, gated combine, store fp32 ----
#pragma unroll
    for (int rs = 0; rs < 2; rs++) {
        int row = wm * 16 + g + rs * 8;
        int h0 = wn * 8 + 2 * tg;
        float res[2];
#pragma unroll
        for (int e = 0; e < 2; e++) {
            int h = h0 + e;
            float v0 = acc3[0][rs * 2 + e] + __ldg(b_z + h);
            float v1 = acc3[1][rs * 2 + e] + __ldg(b_z + 64 + h);
            float v2 = acc3[2][rs * 2 + e] + __ldg(b_z + 128 + h);
            float v3 = acc3[3][rs * 2 + e] + __ldg(b_z + 192 + h);
            float mx = fmaxf(fmaxf(v0, v1), fmaxf(v2, v3));
            float e0 = __expf(v0 - mx), e1 = __expf(v1 - mx);
            float e2 = __expf(v2 - mx), e3 = __expf(v3 - mx);
            float inv = 1.f / (e0 + e1 + e2 + e3);
            float hh = rd_split(AHI, ALO, row, h, SAB);
            float hl = rd_split(AHI, ALO, row, 64 + h, SAB);
            float hr = rd_split(AHI, ALO, row, 128 + h, SAB);
            float uu = rd_split(AHI, ALO, row, 192 + h, SAB);
            res[e] = (e0 * hh + e1 * hl + e2 * hr + e3 * uu) * inv;
        }
        *(float2*)(up_out + (size_t)(r0 + row) * 64 + h0) = make_float2(res[0], res[1]);
    }
}

static int smem_sz(int rows) {
    return rows * SAB * 2 + rows * SRB * 2 + 256 * SBB * 2 + rows * 8 * 4 + 64 * 8 * 4 + 256;
}

extern "C" void kernel_launch(void* const* d_in, const int* in_sizes, int n_in,
                              void* d_out, int out_size) {
    const float* contents = (const float*)d_in[0];
    const float* W_u = (const float*)d_in[1];
    const float* b_u = (const float*)d_in[2];
    const float* W_r = (const float*)d_in[3];
    const float* b_r = (const float*)d_in[4];
    const float* W_h = (const float*)d_in[5];
    const float* b_h = (const float*)d_in[6];
    const float* W_z = (const float*)d_in[7];
    const float* b_z = (const float*)d_in[8];
    float* out = (float*)d_out;

    float *upA = nullptr, *upB = nullptr;
    cudaGetSymbolAddress((void**)&upA, g_upA);
    cudaGetSymbolAddress((void**)&upB, g_upB);
    unsigned short *wrh, *wrl, *whh, *whl, *wzh, *wzl;
    cudaGetSymbolAddress((void**)&wrh, g_Wr_hi); cudaGetSymbolAddress((void**)&wrl, g_Wr_lo);
    cudaGetSymbolAddress((void**)&whh, g_Wh_hi); cudaGetSymbolAddress((void**)&whl, g_Wh_lo);
    cudaGetSymbolAddress((void**)&wzh, g_Wz_hi); cudaGetSymbolAddress((void**)&wzl, g_Wz_lo);

    const int smemBig = smem_sz(64), smemSmall = smem_sz(32);
    cudaFuncSetAttribute(grnn_level_kernel<1024>,
                         cudaFuncAttributeMaxDynamicSharedMemorySize, smemBig);
    cudaFuncSetAttribute(grnn_level_kernel<512>,
                         cudaFuncAttributeMaxDynamicSharedMemorySize, smemSmall);

    prep_weights<<<(114688 + 255) / 256, 256>>>(W_r, W_h, W_z);

    // Level 12 (top): up = u
    {
        int n = 64 << 12;
        size_t off = (size_t)64 * ((1 << 12) - 1) * 7;
        int total = n * 64;
        grnn_top_kernel<<<(total + 255) / 256, 256>>>(contents + off, W_u, b_u, upA, n);
    }

    // Levels 11..0
    const float* prev = upA;
    for (int j = 11; j >= 0; j--) {
        int n = 64 << j;
        size_t off = (size_t)64 * ((1 << j) - 1) * 7;
        float* outp = (j == 0) ? out : ((j & 1) ? upB : upA);
        if (n >= 16384) {
            grnn_level_kernel<1024><<<n / 64, 1024, smemBig>>>(
                contents + off, prev, outp,
                W_u, b_u, wrh, wrl, b_r, whh, whl, b_h, wzh, wzl, b_z);
        } else {
            grnn_level_kernel<512><<<n / 32, 512, smemSmall>>>(
                contents + off, prev, outp,
                W_u, b_u, wrh, wrl, b_r, whh, whl, b_h, wzh, wzl, b_z);
        }
        prev = outp;
    }
}

// round 11
// speedup vs baseline: 2.5819x; 1.0656x over previous
#include <cuda_runtime.h>
#include <cuda_bf16.h>
#include <math.h>

// GRNNTransformGated via mma.sync.m16n8k16 bf16 (3-pass split ~ fp32 precision).
// K-outer GEMMs, pre-split weights, ldmatrix fragments, interleaved MMA issue
// (RAW distance 6-8), register-prefetched B staging.
// NT=512 (16 warps, 2m x 8n, MT=2) big levels; NT=256 (1m x 8n, MT=2) small.

#define SAB 528   // A buf row stride bytes; (528/4)%32=4 -> ldmatrix conflict-free
#define SRB 400   // rx buf row stride bytes; (400/4)%32=4
#define SBB 144   // B k-tile row stride bytes; (144/4)%32=4

__device__ float g_upA[262144 * 64];
__device__ float g_upB[131072 * 64];

// pre-split weights (bf16 hi/lo), [n][K] row-major
__device__ unsigned short g_Wr_hi[36864], g_Wr_lo[36864];
__device__ unsigned short g_Wh_hi[12288], g_Wh_lo[12288];
__device__ unsigned short g_Wz_hi[65536], g_Wz_lo[65536];

__device__ __forceinline__ void split_pack(float a, float b, unsigned& hi, unsigned& lo) {
    __nv_bfloat16 ha = __float2bfloat16(a), hb = __float2bfloat16(b);
    __nv_bfloat16 la = __float2bfloat16(a - __bfloat162float(ha));
    __nv_bfloat16 lb = __float2bfloat16(b - __bfloat162float(hb));
    hi = (unsigned)__bfloat16_as_ushort(ha) | ((unsigned)__bfloat16_as_ushort(hb) << 16);
    lo = (unsigned)__bfloat16_as_ushort(la) | ((unsigned)__bfloat16_as_ushort(lb) << 16);
}
__device__ __forceinline__ float rd_split(const char* hi, const char* lo, int row, int col, int strideB) {
    return __bfloat162float(*(const __nv_bfloat16*)(hi + row * strideB + col * 2)) +
           __bfloat162float(*(const __nv_bfloat16*)(lo + row * strideB + col * 2));
}
__device__ __forceinline__ unsigned smem_u32(const void* p) {
    unsigned a;
    asm("{ .reg .u64 t; cvta.to.shared.u64 t, %1; cvt.u32.u64 %0, t; }" : "=r"(a) : "l"(p));
    return a;
}
__device__ __forceinline__ void mma16816(float* c, const unsigned* a, const unsigned* b) {
    asm volatile("mma.sync.aligned.m16n8k16.row.col.f32.bf16.bf16.f32 "
                 "{%0,%1,%2,%3}, {%4,%5,%6,%7}, {%8,%9}, {%0,%1,%2,%3};"
                 : "+f"(c[0]), "+f"(c[1]), "+f"(c[2]), "+f"(c[3])
                 : "r"(a[0]), "r"(a[1]), "r"(a[2]), "r"(a[3]), "r"(b[0]), "r"(b[1]));
}
#define LDSM_X4(d, addr) \
    asm volatile("ldmatrix.sync.aligned.m8n8.x4.shared.b16 {%0,%1,%2,%3}, [%4];" \
                 : "=r"((d)[0]), "=r"((d)[1]), "=r"((d)[2]), "=r"((d)[3]) : "r"(addr))
#define LDSM_X2(d, addr) \
    asm volatile("ldmatrix.sync.aligned.m8n8.x2.shared.b16 {%0,%1}, [%2];" \
                 : "=r"((d)[0]), "=r"((d)[1]) : "r"(addr))

// ---------------- weight prep: fp32 -> bf16 hi/lo (once per launch) ----------------
__global__ void prep_weights(const float* __restrict__ W_r,
                             const float* __restrict__ W_h,
                             const float* __restrict__ W_z) {
    int i = blockIdx.x * blockDim.x + threadIdx.x;
    float v; unsigned short* ph; unsigned short* pl; int k;
    if (i < 36864)       { v = W_r[i];            ph = g_Wr_hi; pl = g_Wr_lo; k = i; }
    else if (i < 49152)  { v = W_h[i - 36864];    ph = g_Wh_hi; pl = g_Wh_lo; k = i - 36864; }
    else if (i < 114688) { v = W_z[i - 49152];    ph = g_Wz_hi; pl = g_Wz_lo; k = i - 49152; }
    else return;
    __nv_bfloat16 h = __float2bfloat16(v);
    __nv_bfloat16 l = __float2bfloat16(v - __bfloat162float(h));
    ph[k] = __bfloat16_as_ushort(h);
    pl[k] = __bfloat16_as_ushort(l);
}

// register prefetch of a B k-tile (NR virtual rows x 64 k, bf16 hi/lo)
template <int NT>
struct PF {
    static const int MAXE = 2048 / NT;
    uint4 h[MAXE], l[MAXE];
    // remap=false: src row n, cols k0+kq. remap=true (stacked W_h): row n&63, cols (n>>6)*64+kq
    __device__ __forceinline__ void load(const unsigned short* __restrict__ Whi,
                                         const unsigned short* __restrict__ Wlo,
                                         int NR, int Ksrc, int k0, int t, bool remap) {
#pragma unroll
        for (int i = 0; i < MAXE; i++) {
            int e = t + i * NT;
            if (e < NR * 8) {
                int n = e >> 3, kq = (e & 7) * 8;
                int sr = remap ? (n & 63) : n;
                int sk = remap ? ((n >> 6) * 64 + kq) : (k0 + kq);
                h[i] = *(const uint4*)(Whi + (size_t)sr * Ksrc + sk);
                l[i] = *(const uint4*)(Wlo + (size_t)sr * Ksrc + sk);
            }
        }
    }
    __device__ __forceinline__ void store(char* BHI, char* BLO, int NR, int t) {
#pragma unroll
        for (int i = 0; i < MAXE; i++) {
            int e = t + i * NT;
            if (e < NR * 8) {
                int n = e >> 3, kq = (e & 7) * 8;
                *(uint4*)(BHI + n * SBB + kq * 2) = h[i];
                *(uint4*)(BLO + n * SBB + kq * 2) = l[i];
            }
        }
    }
};

// ---------------- top level (j=12) ----------------
__global__ void grnn_top_kernel(const float* __restrict__ contents,
                                const float* __restrict__ W_u,
                                const float* __restrict__ b_u,
                                float* __restrict__ up, int n) {
    int idx = blockIdx.x * blockDim.x + threadIdx.x;
    if (idx >= n * 64) return;
    int i = idx >> 6, h = idx & 63;
    const float* c = contents + (size_t)i * 7;
    const float* w = W_u + h * 7;
    float acc = b_u[h];
#pragma unroll
    for (int f = 0; f < 7; f++) acc = fmaf(__ldg(c + f), __ldg(w + f), acc);
    up[idx] = fmaxf(acc, 0.f);
}

// ---------------- fused level kernel: ROWS = NT/8 rows, MT=2 per warp ----------------
template <int NT>
__global__ __launch_bounds__(NT, 1) void grnn_level_kernel(
    const float* __restrict__ contents,
    const float* __restrict__ up_prev,
    float* __restrict__ up_out,
    const float* __restrict__ W_u, const float* __restrict__ b_u,
    const unsigned short* __restrict__ Wr_hi, const unsigned short* __restrict__ Wr_lo,
    const float* __restrict__ b_r,
    const unsigned short* __restrict__ Wh_hi, const unsigned short* __restrict__ Wh_lo,
    const float* __restrict__ b_h,
    const unsigned short* __restrict__ Wz_hi, const unsigned short* __restrict__ Wz_lo,
    const float* __restrict__ b_z)
{
    constexpr int ROWS = NT / 8;             // 512 -> 64, 256 -> 32
    constexpr int MT = 2;
    constexpr int OF_ALO = ROWS * SAB;
    constexpr int OF_RHI = OF_ALO + ROWS * SAB;
    constexpr int OF_RLO = OF_RHI + ROWS * SRB;
    constexpr int OF_BHI = OF_RLO + ROWS * SRB;
    constexpr int OF_BLO = OF_BHI + 256 * SBB;
    constexpr int OF_CS  = OF_BLO + 256 * SBB;
    constexpr int OF_WU  = OF_CS + ROWS * 8 * 4;
    constexpr int OF_BUS = OF_WU + 64 * 8 * 4;

    extern __shared__ char sm[];
    char* AHI = sm;            char* ALO = sm + OF_ALO;
    char* RHI = sm + OF_RHI;   char* RLO = sm + OF_RLO;
    char* BHI = sm + OF_BHI;   char* BLO = sm + OF_BLO;
    float* cs  = (float*)(sm + OF_CS);
    float* wu  = (float*)(sm + OF_WU);
    float* bus = (float*)(sm + OF_BUS);

    const unsigned smb = smem_u32(sm);
    const unsigned uAHI = smb, uALO = smb + OF_ALO;
    const unsigned uRHI = smb + OF_RHI, uRLO = smb + OF_RLO;
    const unsigned uBHI = smb + OF_BHI, uBLO = smb + OF_BLO;

    const int t = threadIdx.x, lane = t & 31, w = t >> 5;
    const int wm = w >> 3, wn = w & 7, g = lane >> 2, tg = lane & 3;
    const int l16 = lane & 15;
    const unsigned aSel = ((lane >> 4) & 1) * 16;
    const unsigned bSel = ((lane >> 3) & 1) * 16;
    const int r0 = blockIdx.x * ROWS;

    PF<NT> pf;
    pf.load(Wr_hi, Wr_lo, 192, 192, 0, t, false);   // W_r kc=0 in flight during phase 0

    // ---- phase 0a ----
    for (int idx = t; idx < ROWS * 7; idx += NT) {
        int i = idx / 7, f = idx % 7;
        cs[i * 8 + f] = contents[(size_t)(r0 + i) * 7 + f];
    }
    for (int idx = t; idx < 64 * 7; idx += NT) wu[(idx / 7) * 8 + (idx % 7)] = W_u[idx];
    if (t < 64) bus[t] = b_u[t];
    for (int idx = t; idx < ROWS * 32; idx += NT) {
        int i = idx >> 5, q = idx & 31, side = q >> 4, qq = q & 15;
        float4 v = *(const float4*)(up_prev + ((size_t)2 * (r0 + i) + side) * 64 + qq * 4);
        unsigned h0, l0, h1, l1;
        split_pack(v.x, v.y, h0, l0); split_pack(v.z, v.w, h1, l1);
        int col = 64 + side * 64 + qq * 4;
        *(uint2*)(AHI + i * SAB + col * 2) = make_uint2(h0, h1);
        *(uint2*)(ALO + i * SAB + col * 2) = make_uint2(l0, l1);
    }
    __syncthreads();
    // ---- phase 0b: u = relu(c @ W_u^T + b_u) -> cols 192..255 ----
    for (int idx = t; idx < ROWS * 32; idx += NT) {
        int i = idx >> 5, cp = idx & 31;
        float a0 = bus[2 * cp], a1 = bus[2 * cp + 1];
#pragma unroll
        for (int f = 0; f < 7; f++) {
            float cv = cs[i * 8 + f];
            a0 = fmaf(cv, wu[(2 * cp) * 8 + f], a0);
            a1 = fmaf(cv, wu[(2 * cp + 1) * 8 + f], a1);
        }
        a0 = fmaxf(a0, 0.f); a1 = fmaxf(a1, 0.f);
        unsigned hi, lo; split_pack(a0, a1, hi, lo);
        *(unsigned*)(AHI + i * SAB + (192 + 2 * cp) * 2) = hi;
        *(unsigned*)(ALO + i * SAB + (192 + 2 * cp) * 2) = lo;
    }

    // ---- GEMM1: rx = sigmoid(hhu @ W_r^T + b_r) * hhu; K-outer, 3 N-chunks ----
    float acc1[3][MT][4] = {};
    for (int kc = 0; kc < 3; kc++) {
        if (kc > 0) __syncthreads();            // prior B reads done
        pf.store(BHI, BLO, 192, t);
        if (kc < 2) pf.load(Wr_hi, Wr_lo, 192, 192, (kc + 1) * 64, t, false);
        else        pf.load(Wh_hi, Wh_lo, 192, 192, 0, t, true);   // stacked W_h next
        __syncthreads();
#pragma unroll
        for (int kk = 0; kk < 4; kk++) {
            unsigned ah[MT][4], al[MT][4];
#pragma unroll
            for (int mt = 0; mt < MT; mt++) {
                unsigned off = (unsigned)(((wm * MT + mt) * 16 + l16) * SAB
                                          + (64 + kc * 64 + kk * 16) * 2) + aSel;
                LDSM_X4(ah[mt], uAHI + off);
                LDSM_X4(al[mt], uALO + off);
            }
            unsigned bh[3][2], bl[3][2];
#pragma unroll
            for (int c = 0; c < 3; c++) {
                unsigned bo = (unsigned)((c * 64 + wn * 8 + (lane & 7)) * SBB + kk * 32) + bSel;
                LDSM_X2(bh[c], uBHI + bo);
                LDSM_X2(bl[c], uBLO + bo);
            }
            // interleaved passes: RAW distance 6
#pragma unroll
            for (int c = 0; c < 3; c++)
#pragma unroll
                for (int mt = 0; mt < MT; mt++) mma16816(acc1[c][mt], ah[mt], bh[c]);
#pragma unroll
            for (int c = 0; c < 3; c++)
#pragma unroll
                for (int mt = 0; mt < MT; mt++) mma16816(acc1[c][mt], ah[mt], bl[c]);
#pragma unroll
            for (int c = 0; c < 3; c++)
#pragma unroll
                for (int mt = 0; mt < MT; mt++) mma16816(acc1[c][mt], al[mt], bh[c]);
        }
    }
    // epilogue 1: rx -> RHI/RLO (unique rows per thread; no sync needed before)
#pragma unroll
    for (int c = 0; c < 3; c++)
#pragma unroll
        for (int mt = 0; mt < MT; mt++)
#pragma unroll
            for (int rs = 0; rs < 2; rs++) {
                int row = (wm * MT + mt) * 16 + g + rs * 8;
                int o0 = c * 64 + wn * 8 + 2 * tg;
                float z0 = acc1[c][mt][rs * 2 + 0] + __ldg(b_r + o0);
                float z1 = acc1[c][mt][rs * 2 + 1] + __ldg(b_r + o0 + 1);
                float s0 = 1.f / (1.f + __expf(-z0));
                float s1 = 1.f / (1.f + __expf(-z1));
                float x0 = s0 * rd_split(AHI, ALO, row, 64 + o0, SAB);
                float x1 = s1 * rd_split(AHI, ALO, row, 64 + o0 + 1, SAB);
                unsigned hi, lo; split_pack(x0, x1, hi, lo);
                *(unsigned*)(RHI + row * SRB + o0 * 2) = hi;
                *(unsigned*)(RLO + row * SRB + o0 * 2) = lo;
            }
    __syncthreads();                         // GEMM1 B reads done + rx visible
    pf.store(BHI, BLO, 192, t);              // stacked W_h
    pf.load(Wz_hi, Wz_lo, 256, 256, 0, t, false);
    __syncthreads();

    // ---- GEMM2: h_H = relu(rx @ W_h^T + b_h) -> AHI cols 0..63 ----
    {
        float acc[MT][4] = {};
#pragma unroll
        for (int kk = 0; kk < 12; kk++) {
            int kt = kk >> 2, k2 = kk & 3;
            unsigned ah[MT][4], al[MT][4];
#pragma unroll
            for (int mt = 0; mt < MT; mt++) {
                unsigned off = (unsigned)(((wm * MT + mt) * 16 + l16) * SRB + kk * 32) + aSel;
                LDSM_X4(ah[mt], uRHI + off);
                LDSM_X4(al[mt], uRLO + off);
            }
            unsigned bo = (unsigned)((kt * 64 + wn * 8 + (lane & 7)) * SBB + k2 * 32) + bSel;
            unsigned bh[2], bl[2];
            LDSM_X2(bh, uBHI + bo);
            LDSM_X2(bl, uBLO + bo);
#pragma unroll
            for (int mt = 0; mt < MT; mt++) mma16816(acc[mt], ah[mt], bh);
#pragma unroll
            for (int mt = 0; mt < MT; mt++) mma16816(acc[mt], ah[mt], bl);
#pragma unroll
            for (int mt = 0; mt < MT; mt++) mma16816(acc[mt], al[mt], bh);
        }
#pragma unroll
        for (int mt = 0; mt < MT; mt++)
#pragma unroll
            for (int rs = 0; rs < 2; rs++) {
                int row = (wm * MT + mt) * 16 + g + rs * 8;
                int h0 = wn * 8 + 2 * tg;
                float v0 = fmaxf(acc[mt][rs * 2 + 0] + __ldg(b_h + h0), 0.f);
                float v1 = fmaxf(acc[mt][rs * 2 + 1] + __ldg(b_h + h0 + 1), 0.f);
                unsigned hi, lo; split_pack(v0, v1, hi, lo);
                *(unsigned*)(AHI + row * SAB + h0 * 2) = hi;
                *(unsigned*)(ALO + row * SAB + h0 * 2) = lo;
            }
    }

    // ---- GEMM3: z = [h_H | hhu] @ W_z^T + b_z; K-outer, 4 N-chunks ----
    float acc3[4][MT][4] = {};
    for (int kc = 0; kc < 4; kc++) {
        __syncthreads();                    // prior B reads done; hH visible (kc=0)
        pf.store(BHI, BLO, 256, t);
        if (kc < 3) pf.load(Wz_hi, Wz_lo, 256, 256, (kc + 1) * 64, t, false);
        __syncthreads();
#pragma unroll
        for (int kk = 0; kk < 4; kk++) {
            unsigned ah[MT][4], al[MT][4];
#pragma unroll
            for (int mt = 0; mt < MT; mt++) {
                unsigned off = (unsigned)(((wm * MT + mt) * 16 + l16) * SAB
                                          + (kc * 64 + kk * 16) * 2) + aSel;
                LDSM_X4(ah[mt], uAHI + off);
                LDSM_X4(al[mt], uALO + off);
            }
            unsigned bh[4][2], bl[4][2];
#pragma unroll
            for (int c = 0; c < 4; c++) {
                unsigned bo = (unsigned)((c * 64 + wn * 8 + (lane & 7)) * SBB + kk * 32) + bSel;
                LDSM_X2(bh[c], uBHI + bo);
                LDSM_X2(bl[c], uBLO + bo);
            }
#pragma unroll
            for (int c = 0; c < 4; c++)
#pragma unroll
                for (int mt = 0; mt < MT; mt++) mma16816(acc3[c][mt], ah[mt], bh[c]);
#pragma unroll
            for (int c = 0; c < 4; c++)
#pragma unroll
                for (int mt = 0; mt < MT; mt++) mma16816(acc3[c][mt], ah[mt], bl[c]);
#pragma unroll
            for (int c = 0; c < 4; c++)
#pragma unroll
                for (int mt = 0; mt < MT; mt++) mma16816(acc3[c][mt], al[mt], bh[c]);
        }
    }

    // ---- final: softmax over 4 groups, gated combine, store fp32 ----
#pragma unroll
    for (int mt = 0; mt < MT; mt++)
#pragma unroll
        for (int rs = 0; rs < 2; rs++) {
            int row = (wm * MT + mt) * 16 + g + rs * 8;
            int h0 = wn * 8 + 2 * tg;
            float res[2];
#pragma unroll
            for (int e = 0; e < 2; e++) {
                int h = h0 + e;
                float v0 = acc3[0][mt][rs * 2 + e] + __ldg(b_z + h);
                float v1 = acc3[1][mt][rs * 2 + e] + __ldg(b_z + 64 + h);
                float v2 = acc3[2][mt][rs * 2 + e] + __ldg(b_z + 128 + h);
                float v3 = acc3[3][mt][rs * 2 + e] + __ldg(b_z + 192 + h);
                float mx = fmaxf(fmaxf(v0, v1), fmaxf(v2, v3));
                float e0 = __expf(v0 - mx), e1 = __expf(v1 - mx);
                float e2 = __expf(v2 - mx), e3 = __expf(v3 - mx);
                float inv = 1.f / (e0 + e1 + e2 + e3);
                float hh = rd_split(AHI, ALO, row, h, SAB);
                float hl = rd_split(AHI, ALO, row, 64 + h, SAB);
                float hr = rd_split(AHI, ALO, row, 128 + h, SAB);
                float uu = rd_split(AHI, ALO, row, 192 + h, SAB);
                res[e] = (e0 * hh + e1 * hl + e2 * hr + e3 * uu) * inv;
            }
            *(float2*)(up_out + (size_t)(r0 + row) * 64 + h0) = make_float2(res[0], res[1]);
        }
}

static int smem_sz(int rows) {
    return rows * SAB * 2 + rows * SRB * 2 + 256 * SBB * 2 + rows * 8 * 4 + 64 * 8 * 4 + 256;
}

extern "C" void kernel_launch(void* const* d_in, const int* in_sizes, int n_in,
                              void* d_out, int out_size) {
    const float* contents = (const float*)d_in[0];
    const float* W_u = (const float*)d_in[1];
    const float* b_u = (const float*)d_in[2];
    const float* W_r = (const float*)d_in[3];
    const float* b_r = (const float*)d_in[4];
    const float* W_h = (const float*)d_in[5];
    const float* b_h = (const float*)d_in[6];
    const float* W_z = (const float*)d_in[7];
    const float* b_z = (const float*)d_in[8];
    float* out = (float*)d_out;

    float *upA = nullptr, *upB = nullptr;
    cudaGetSymbolAddress((void**)&upA, g_upA);
    cudaGetSymbolAddress((void**)&upB, g_upB);
    unsigned short *wrh, *wrl, *whh, *whl, *wzh, *wzl;
    cudaGetSymbolAddress((void**)&wrh, g_Wr_hi); cudaGetSymbolAddress((void**)&wrl, g_Wr_lo);
    cudaGetSymbolAddress((void**)&whh, g_Wh_hi); cudaGetSymbolAddress((void**)&whl, g_Wh_lo);
    cudaGetSymbolAddress((void**)&wzh, g_Wz_hi); cudaGetSymbolAddress((void**)&wzl, g_Wz_lo);

    const int smemBig = smem_sz(64), smemSmall = smem_sz(32);
    cudaFuncSetAttribute(grnn_level_kernel<512>,
                         cudaFuncAttributeMaxDynamicSharedMemorySize, smemBig);
    cudaFuncSetAttribute(grnn_level_kernel<256>,
                         cudaFuncAttributeMaxDynamicSharedMemorySize, smemSmall);

    prep_weights<<<(114688 + 255) / 256, 256>>>(W_r, W_h, W_z);

    // Level 12 (top): up = u
    {
        int n = 64 << 12;
        size_t off = (size_t)64 * ((1 << 12) - 1) * 7;
        int total = n * 64;
        grnn_top_kernel<<<(total + 255) / 256, 256>>>(contents + off, W_u, b_u, upA, n);
    }

    // Levels 11..0
    const float* prev = upA;
    for (int j = 11; j >= 0; j--) {
        int n = 64 << j;
        size_t off = (size_t)64 * ((1 << j) - 1) * 7;
        float* outp = (j == 0) ? out : ((j & 1) ? upB : upA);
        if (n >= 16384) {
            grnn_level_kernel<512><<<n / 64, 512, smemBig>>>(
                contents + off, prev, outp,
                W_u, b_u, wrh, wrl, b_r, whh, whl, b_h, wzh, wzl, b_z);
        } else {
            grnn_level_kernel<256><<<n / 32, 256, smemSmall>>>(
                contents + off, prev, outp,
                W_u, b_u, wrh, wrl, b_r, whh, whl, b_h, wzh, wzl, b_z);
        }
        prev = outp;
    }
}